// round 3
// baseline (speedup 1.0000x reference)
#include <cuda_runtime.h>
#include <math.h>

#define FULL 0xffffffffu

// Problem constants
constexpr int B_ = 4;
constexpr int P_ = 2048;
constexpr int NPOS = B_ * P_;           // 8192

// Scratch (device globals; no allocation in kernel_launch)
__device__ float g_enc_psi[NPOS * 32];
__device__ float g_enc[NPOS * 32];
__device__ float g_aggraw[NPOS * 32];
__device__ float g_u[NPOS * 4];
__device__ float g_num[NPOS * 4 * 32];
__device__ float g_den[NPOS * 4];

// combined[lane] for one position:
//  lanes 0..7 : time encoding sin/cos with divisors 1,1,10,10,100,100,1000,1000
//  lane  8    : value
//  lanes 9..30: one-hot of measurement classes 1..22
__device__ __forceinline__ float combined_lane(float t, float v, int m, int lane) {
    if (lane < 8) {
        float sc;
        switch (lane >> 1) {
            case 0:  sc = 1.0f;   break;
            case 1:  sc = 0.1f;   break;
            case 2:  sc = 0.01f;  break;
            default: sc = 0.001f; break;
        }
        float r = t * sc;
        return (lane & 1) ? cosf(r) : sinf(r);
    } else if (lane == 8) {
        return v;
    } else if (lane < 31) {
        return (m == lane - 8) ? 1.0f : 0.0f;
    }
    return 0.0f;
}

// ---------------------------------------------------------------------------
// K1: per-position features + psi MLP + phi MLP.
// One warp per position; lane = hidden channel (32). Weights staged in smem.
// ---------------------------------------------------------------------------
__global__ __launch_bounds__(256) void k1_feat_mlps(
    const float* __restrict__ times, const float* __restrict__ values,
    const int* __restrict__ meas, const float* __restrict__ mask,
    const float* __restrict__ pw1, const float* __restrict__ pb1,
    const float* __restrict__ pw2, const float* __restrict__ pb2,
    const float* __restrict__ fw1, const float* __restrict__ fb1,
    const float* __restrict__ fw2, const float* __restrict__ fb2)
{
    __shared__ float s_pw1[31 * 32], s_pw2[32 * 32];
    __shared__ float s_fw1[31 * 32], s_fw2[32 * 32];
    __shared__ float s_pb1[32], s_pb2[32], s_fb1[32], s_fb2[32];

    int tid = threadIdx.x;
    for (int i = tid; i < 31 * 32; i += 256) { s_pw1[i] = pw1[i]; s_fw1[i] = fw1[i]; }
    for (int i = tid; i < 32 * 32; i += 256) { s_pw2[i] = pw2[i]; s_fw2[i] = fw2[i]; }
    if (tid < 32) { s_pb1[tid] = pb1[tid]; s_pb2[tid] = pb2[tid];
                    s_fb1[tid] = fb1[tid]; s_fb2[tid] = fb2[tid]; }
    __syncthreads();

    int lane = tid & 31;
    int pos  = blockIdx.x * 8 + (tid >> 5);   // grid = 1024 blocks -> 8192 positions

    float t  = times[pos];
    float v  = values[pos];
    float mk = mask[pos];
    int   m  = meas[pos];

    float xm = combined_lane(t, v, m, lane) * mk;   // (x * mask)

    // psi: h1 = relu(xm @ w1 + b1); h2 = relu(h1*mask @ w2 + b2); out = h2*mask
    float a = s_pb1[lane];
    #pragma unroll
    for (int i = 0; i < 31; i++)
        a += __shfl_sync(FULL, xm, i) * s_pw1[i * 32 + lane];
    float h = fmaxf(a, 0.0f) * mk;
    a = s_pb2[lane];
    #pragma unroll
    for (int k = 0; k < 32; k++)
        a += __shfl_sync(FULL, h, k) * s_pw2[k * 32 + lane];
    g_enc_psi[pos * 32 + lane] = fmaxf(a, 0.0f) * mk;

    // phi (same structure)
    a = s_fb1[lane];
    #pragma unroll
    for (int i = 0; i < 31; i++)
        a += __shfl_sync(FULL, xm, i) * s_fw1[i * 32 + lane];
    h = fmaxf(a, 0.0f) * mk;
    a = s_fb2[lane];
    #pragma unroll
    for (int k = 0; k < 32; k++)
        a += __shfl_sync(FULL, h, k) * s_fw2[k * 32 + lane];
    g_enc[pos * 32 + lane] = fmaxf(a, 0.0f) * mk;
}

// ---------------------------------------------------------------------------
// K2: cumulative mean of enc_psi over P per (batch, channel).
// One warp per (b,c) = 128 warps; lane handles 64 consecutive positions;
// two-phase: per-lane partial sum -> warp exclusive scan -> write pass.
// ---------------------------------------------------------------------------
__global__ __launch_bounds__(256) void k2_cummean(const float* __restrict__ mask)
{
    int tid  = threadIdx.x;
    int lane = tid & 31;
    int w    = blockIdx.x * 8 + (tid >> 5);
    if (w >= B_ * 32) return;
    int b = w >> 5, c = w & 31;

    const float* src  = g_enc_psi + b * P_ * 32 + c;
    float*       dst  = g_aggraw  + b * P_ * 32 + c;
    const float* mptr = mask + b * P_;

    int p0 = lane * 64;
    float s = 0.0f;
    #pragma unroll 4
    for (int j = 0; j < 64; j++) s += src[(p0 + j) * 32];

    // inclusive warp scan -> exclusive
    float run = s;
    #pragma unroll
    for (int off = 1; off < 32; off <<= 1) {
        float tpart = __shfl_up_sync(FULL, run, off);
        if (lane >= off) run += tpart;
    }
    float acc = run - s;

    for (int j = 0; j < 64; j++) {
        int p = p0 + j;
        acc += src[p * 32];
        dst[p * 32] = acc / (float)(p + 1) * mptr[p];
    }
}

// ---------------------------------------------------------------------------
// K3: agg = (agg_raw @ arho + b)*mask; keys = [combined, agg] @ W_k * mask;
// preattn[h] = sum_d keys[d*4+h]*W_q[h,d] / 4 * mask;  u = exp(preattn).
// One warp per position; lane j computes keys j and j+32.
// ---------------------------------------------------------------------------
__global__ __launch_bounds__(256) void k3_preattn(
    const float* __restrict__ times, const float* __restrict__ values,
    const int* __restrict__ meas, const float* __restrict__ mask,
    const float* __restrict__ arw, const float* __restrict__ arb,
    const float* __restrict__ wk, const float* __restrict__ wq)
{
    __shared__ float s_ar[32 * 32], s_wk[63 * 64];
    __shared__ float s_ab[32], s_wq[64];

    int tid = threadIdx.x;
    for (int i = tid; i < 32 * 32; i += 256) s_ar[i] = arw[i];
    for (int i = tid; i < 63 * 64; i += 256) s_wk[i] = wk[i];
    if (tid < 32) s_ab[tid] = arb[tid];
    if (tid < 64) s_wq[tid] = wq[tid];
    __syncthreads();

    int lane = tid & 31;
    int pos  = blockIdx.x * 8 + (tid >> 5);

    float t  = times[pos];
    float v  = values[pos];
    float mk = mask[pos];
    int   m  = meas[pos];

    float x  = combined_lane(t, v, m, lane);   // RAW combined (no mask) feeds W_k
    float ar = g_aggraw[pos * 32 + lane];

    float agg = s_ab[lane];
    #pragma unroll
    for (int k = 0; k < 32; k++)
        agg += __shfl_sync(FULL, ar, k) * s_ar[k * 32 + lane];
    agg *= mk;

    float a0 = 0.0f, a1 = 0.0f;
    #pragma unroll
    for (int i = 0; i < 31; i++) {
        float c = __shfl_sync(FULL, x, i);
        a0 += c * s_wk[i * 64 + lane];
        a1 += c * s_wk[i * 64 + lane + 32];
    }
    #pragma unroll
    for (int c = 0; c < 32; c++) {
        float g = __shfl_sync(FULL, agg, c);
        a0 += g * s_wk[(31 + c) * 64 + lane];
        a1 += g * s_wk[(31 + c) * 64 + lane + 32];
    }
    a0 *= mk; a1 *= mk;   // keys * mask

    // keys flat index k = d*4 + h : lane -> (h=lane&3, d=lane>>2); lane+32 -> same h, d+8
    int hh = lane & 3, dd = lane >> 2;
    float part = a0 * s_wq[hh * 16 + dd] + a1 * s_wq[hh * 16 + dd + 8];
    part += __shfl_xor_sync(FULL, part, 4);
    part += __shfl_xor_sync(FULL, part, 8);
    part += __shfl_xor_sync(FULL, part, 16);

    float pre = part * 0.25f * mk;   // / sqrt(16), then * mask
    if (lane < 4) g_u[pos * 4 + lane] = expf(pre);
}

// ---------------------------------------------------------------------------
// K4: causal prefix sums per (b,h):
//   num[p,d] = sum_{q<=p} u[q]*enc[q,d]   (lane = d)
//   den[p]   = sum_{q<=p} u[q]
// Block per (b,h) (16 blocks), 8 warps x 256 positions; two-phase scan.
// ---------------------------------------------------------------------------
__global__ __launch_bounds__(256) void k4_scan()
{
    __shared__ float s_tn[8][32];
    __shared__ float s_td[8];

    int b = blockIdx.x >> 2, h = blockIdx.x & 3;
    int w = threadIdx.x >> 5, lane = threadIdx.x & 31;

    const float* up = g_u   + b * P_ * 4  + h;
    const float* ep = g_enc + b * P_ * 32 + lane;
    int pb = w * 256;

    float an = 0.0f, ad = 0.0f;
    for (int j = 0; j < 256; j++) {
        int p = pb + j;
        float uu = up[p * 4];
        an += uu * ep[p * 32];
        ad += uu;
    }
    s_tn[w][lane] = an;
    if (lane == 0) s_td[w] = ad;
    __syncthreads();

    float offn = 0.0f, offd = 0.0f;
    for (int w2 = 0; w2 < w; w2++) { offn += s_tn[w2][lane]; offd += s_td[w2]; }

    an = offn; ad = offd;
    float* np = g_num + (b * P_ * 4 + h) * 32 + lane;
    float* dp = g_den + b * P_ * 4 + h;
    for (int j = 0; j < 256; j++) {
        int p = pb + j;
        float uu = up[p * 4];
        an += uu * ep[p * 32];
        ad += uu;
        np[p * 128] = an;
        if (lane == 0) dp[p * 4] = ad;
    }
}

// ---------------------------------------------------------------------------
// K5: agg2 = (num/den) * mask * mask  (out5*mask, then x*mask inside rho MLP);
// rho: 128 -> 64 relu -> 64 relu; output * mask.
// One warp handles 4 positions (amortizes weight loads 4x). Lane = out ch
// j and j+32. Grid 256 blocks x 8 warps x 4 positions = 8192.
// ---------------------------------------------------------------------------
__global__ __launch_bounds__(256) void k5_rho(
    const float* __restrict__ mask,
    const float* __restrict__ rw1, const float* __restrict__ rb1,
    const float* __restrict__ rw2, const float* __restrict__ rb2,
    float* __restrict__ out)
{
    __shared__ float s_a[8][4][128];
    __shared__ float s_h[8][4][64];

    int w = threadIdx.x >> 5, lane = threadIdx.x & 31;
    int pos0 = (blockIdx.x * 8 + w) * 4;

    float mks[4];
    #pragma unroll
    for (int q = 0; q < 4; q++) {
        int pos = pos0 + q;
        float mk = mask[pos];
        mks[q] = mk;
        #pragma unroll
        for (int h = 0; h < 4; h++) {
            float den = g_den[pos * 4 + h];
            float nm  = g_num[(pos * 4 + h) * 32 + lane];
            s_a[w][q][h * 32 + lane] = nm / den * mk * mk;
        }
    }
    __syncwarp();

    float acc0[4], acc1[4];
    #pragma unroll
    for (int q = 0; q < 4; q++) { acc0[q] = rb1[lane]; acc1[q] = rb1[lane + 32]; }

    for (int k = 0; k < 128; k++) {
        float w0 = rw1[k * 64 + lane];
        float w1 = rw1[k * 64 + lane + 32];
        #pragma unroll
        for (int q = 0; q < 4; q++) {
            float a = s_a[w][q][k];
            acc0[q] += a * w0;
            acc1[q] += a * w1;
        }
    }
    #pragma unroll
    for (int q = 0; q < 4; q++) {
        s_h[w][q][lane]      = fmaxf(acc0[q], 0.0f) * mks[q];
        s_h[w][q][lane + 32] = fmaxf(acc1[q], 0.0f) * mks[q];
    }
    __syncwarp();

    #pragma unroll
    for (int q = 0; q < 4; q++) { acc0[q] = rb2[lane]; acc1[q] = rb2[lane + 32]; }

    for (int k = 0; k < 64; k++) {
        float w0 = rw2[k * 64 + lane];
        float w1 = rw2[k * 64 + lane + 32];
        #pragma unroll
        for (int q = 0; q < 4; q++) {
            float a = s_h[w][q][k];
            acc0[q] += a * w0;
            acc1[q] += a * w1;
        }
    }
    #pragma unroll
    for (int q = 0; q < 4; q++) {
        int pos = pos0 + q;
        out[pos * 64 + lane]      = fmaxf(acc0[q], 0.0f) * mks[q];
        out[pos * 64 + lane + 32] = fmaxf(acc1[q], 0.0f) * mks[q];
    }
}

// ---------------------------------------------------------------------------
extern "C" void kernel_launch(void* const* d_in, const int* in_sizes, int n_in,
                              void* d_out, int out_size)
{
    const float* times   = (const float*)d_in[0];
    const float* values  = (const float*)d_in[1];
    const int*   meas    = (const int*)  d_in[2];
    const float* mask    = (const float*)d_in[3];
    const float* psi_w1  = (const float*)d_in[4];
    const float* psi_b1  = (const float*)d_in[5];
    const float* psi_w2  = (const float*)d_in[6];
    const float* psi_b2  = (const float*)d_in[7];
    const float* arho_w  = (const float*)d_in[8];
    const float* arho_b  = (const float*)d_in[9];
    const float* W_k     = (const float*)d_in[10];
    const float* W_q     = (const float*)d_in[11];
    const float* phi_w1  = (const float*)d_in[12];
    const float* phi_b1  = (const float*)d_in[13];
    const float* phi_w2  = (const float*)d_in[14];
    const float* phi_b2  = (const float*)d_in[15];
    const float* rho_w1  = (const float*)d_in[16];
    const float* rho_b1  = (const float*)d_in[17];
    const float* rho_w2  = (const float*)d_in[18];
    const float* rho_b2  = (const float*)d_in[19];
    float* out = (float*)d_out;

    k1_feat_mlps<<<NPOS / 8, 256>>>(times, values, meas, mask,
                                    psi_w1, psi_b1, psi_w2, psi_b2,
                                    phi_w1, phi_b1, phi_w2, phi_b2);
    k2_cummean<<<16, 256>>>(mask);
    k3_preattn<<<NPOS / 8, 256>>>(times, values, meas, mask,
                                  arho_w, arho_b, W_k, W_q);
    k4_scan<<<16, 256>>>();
    k5_rho<<<256, 256>>>(mask, rho_w1, rho_b1, rho_w2, rho_b2, out);
}

// round 4
// speedup vs baseline: 1.0613x; 1.0613x over previous
#include <cuda_runtime.h>
#include <math.h>

#define FULL 0xffffffffu

// Problem constants
constexpr int B_ = 4;
constexpr int P_ = 2048;
constexpr int NPOS = B_ * P_;           // 8192

// Scratch (device globals; no allocation in kernel_launch)
__device__ float g_enc_psi[NPOS * 32];
__device__ float g_enc[NPOS * 32];
__device__ float g_aggraw[NPOS * 32];
__device__ float g_u[NPOS * 4];
__device__ float g_num[NPOS * 4 * 32];
__device__ float g_den[NPOS * 4];

// combined[lane] for one position:
//  lanes 0..7 : time encoding sin/cos with divisors 1,1,10,10,100,100,1000,1000
//  lane  8    : value
//  lanes 9..30: one-hot of measurement classes 1..22
__device__ __forceinline__ float combined_lane(float t, float v, int m, int lane) {
    if (lane < 8) {
        float sc;
        switch (lane >> 1) {
            case 0:  sc = 1.0f;   break;
            case 1:  sc = 0.1f;   break;
            case 2:  sc = 0.01f;  break;
            default: sc = 0.001f; break;
        }
        float r = t * sc;
        return (lane & 1) ? cosf(r) : sinf(r);
    } else if (lane == 8) {
        return v;
    } else if (lane < 31) {
        return (m == lane - 8) ? 1.0f : 0.0f;
    }
    return 0.0f;
}

// ---------------------------------------------------------------------------
// K1: per-position features + psi MLP + phi MLP.
// One warp per position; lane = hidden channel (32). Weights staged in smem.
// ---------------------------------------------------------------------------
__global__ __launch_bounds__(256) void k1_feat_mlps(
    const float* __restrict__ times, const float* __restrict__ values,
    const int* __restrict__ meas, const float* __restrict__ mask,
    const float* __restrict__ pw1, const float* __restrict__ pb1,
    const float* __restrict__ pw2, const float* __restrict__ pb2,
    const float* __restrict__ fw1, const float* __restrict__ fb1,
    const float* __restrict__ fw2, const float* __restrict__ fb2)
{
    __shared__ float s_pw1[31 * 32], s_pw2[32 * 32];
    __shared__ float s_fw1[31 * 32], s_fw2[32 * 32];
    __shared__ float s_pb1[32], s_pb2[32], s_fb1[32], s_fb2[32];

    int tid = threadIdx.x;
    for (int i = tid; i < 31 * 32; i += 256) { s_pw1[i] = pw1[i]; s_fw1[i] = fw1[i]; }
    for (int i = tid; i < 32 * 32; i += 256) { s_pw2[i] = pw2[i]; s_fw2[i] = fw2[i]; }
    if (tid < 32) { s_pb1[tid] = pb1[tid]; s_pb2[tid] = pb2[tid];
                    s_fb1[tid] = fb1[tid]; s_fb2[tid] = fb2[tid]; }
    __syncthreads();

    int lane = tid & 31;
    int pos  = blockIdx.x * 8 + (tid >> 5);   // grid = 1024 blocks -> 8192 positions

    float t  = times[pos];
    float v  = values[pos];
    float mk = mask[pos];
    int   m  = meas[pos];

    float xm = combined_lane(t, v, m, lane) * mk;   // (x * mask)

    // psi: h1 = relu(xm @ w1 + b1); h2 = relu(h1*mask @ w2 + b2); out = h2*mask
    float a = s_pb1[lane];
    #pragma unroll
    for (int i = 0; i < 31; i++)
        a += __shfl_sync(FULL, xm, i) * s_pw1[i * 32 + lane];
    float h = fmaxf(a, 0.0f) * mk;
    a = s_pb2[lane];
    #pragma unroll
    for (int k = 0; k < 32; k++)
        a += __shfl_sync(FULL, h, k) * s_pw2[k * 32 + lane];
    g_enc_psi[pos * 32 + lane] = fmaxf(a, 0.0f) * mk;

    // phi (same structure)
    a = s_fb1[lane];
    #pragma unroll
    for (int i = 0; i < 31; i++)
        a += __shfl_sync(FULL, xm, i) * s_fw1[i * 32 + lane];
    h = fmaxf(a, 0.0f) * mk;
    a = s_fb2[lane];
    #pragma unroll
    for (int k = 0; k < 32; k++)
        a += __shfl_sync(FULL, h, k) * s_fw2[k * 32 + lane];
    g_enc[pos * 32 + lane] = fmaxf(a, 0.0f) * mk;
}

// ---------------------------------------------------------------------------
// K2: cumulative mean of enc_psi over P per (batch, channel).
// One warp per (b,c) = 128 warps; lane handles 64 consecutive positions;
// two-phase: per-lane partial sum -> warp exclusive scan -> write pass.
// ---------------------------------------------------------------------------
__global__ __launch_bounds__(256) void k2_cummean(const float* __restrict__ mask)
{
    int tid  = threadIdx.x;
    int lane = tid & 31;
    int w    = blockIdx.x * 8 + (tid >> 5);
    if (w >= B_ * 32) return;
    int b = w >> 5, c = w & 31;

    const float* src  = g_enc_psi + b * P_ * 32 + c;
    float*       dst  = g_aggraw  + b * P_ * 32 + c;
    const float* mptr = mask + b * P_;

    int p0 = lane * 64;
    float s = 0.0f;
    #pragma unroll 4
    for (int j = 0; j < 64; j++) s += src[(p0 + j) * 32];

    // inclusive warp scan -> exclusive
    float run = s;
    #pragma unroll
    for (int off = 1; off < 32; off <<= 1) {
        float tpart = __shfl_up_sync(FULL, run, off);
        if (lane >= off) run += tpart;
    }
    float acc = run - s;

    for (int j = 0; j < 64; j++) {
        int p = p0 + j;
        acc += src[p * 32];
        dst[p * 32] = acc / (float)(p + 1) * mptr[p];
    }
}

// ---------------------------------------------------------------------------
// K3: agg = (agg_raw @ arho + b)*mask; keys = [combined, agg] @ W_k * mask;
// preattn[h] = sum_d keys[d*4+h]*W_q[h,d] / 4 * mask;  u = exp(preattn).
// One warp per position; lane j computes keys j and j+32.
// ---------------------------------------------------------------------------
__global__ __launch_bounds__(256) void k3_preattn(
    const float* __restrict__ times, const float* __restrict__ values,
    const int* __restrict__ meas, const float* __restrict__ mask,
    const float* __restrict__ arw, const float* __restrict__ arb,
    const float* __restrict__ wk, const float* __restrict__ wq)
{
    __shared__ float s_ar[32 * 32], s_wk[63 * 64];
    __shared__ float s_ab[32], s_wq[64];

    int tid = threadIdx.x;
    for (int i = tid; i < 32 * 32; i += 256) s_ar[i] = arw[i];
    for (int i = tid; i < 63 * 64; i += 256) s_wk[i] = wk[i];
    if (tid < 32) s_ab[tid] = arb[tid];
    if (tid < 64) s_wq[tid] = wq[tid];
    __syncthreads();

    int lane = tid & 31;
    int pos  = blockIdx.x * 8 + (tid >> 5);

    float t  = times[pos];
    float v  = values[pos];
    float mk = mask[pos];
    int   m  = meas[pos];

    float x  = combined_lane(t, v, m, lane);   // RAW combined (no mask) feeds W_k
    float ar = g_aggraw[pos * 32 + lane];

    float agg = s_ab[lane];
    #pragma unroll
    for (int k = 0; k < 32; k++)
        agg += __shfl_sync(FULL, ar, k) * s_ar[k * 32 + lane];
    agg *= mk;

    float a0 = 0.0f, a1 = 0.0f;
    #pragma unroll
    for (int i = 0; i < 31; i++) {
        float c = __shfl_sync(FULL, x, i);
        a0 += c * s_wk[i * 64 + lane];
        a1 += c * s_wk[i * 64 + lane + 32];
    }
    #pragma unroll
    for (int c = 0; c < 32; c++) {
        float g = __shfl_sync(FULL, agg, c);
        a0 += g * s_wk[(31 + c) * 64 + lane];
        a1 += g * s_wk[(31 + c) * 64 + lane + 32];
    }
    a0 *= mk; a1 *= mk;   // keys * mask

    // keys flat index k = d*4 + h : lane -> (h=lane&3, d=lane>>2); lane+32 -> same h, d+8
    int hh = lane & 3, dd = lane >> 2;
    float part = a0 * s_wq[hh * 16 + dd] + a1 * s_wq[hh * 16 + dd + 8];
    part += __shfl_xor_sync(FULL, part, 4);
    part += __shfl_xor_sync(FULL, part, 8);
    part += __shfl_xor_sync(FULL, part, 16);

    float pre = part * 0.25f * mk;   // / sqrt(16), then * mask
    if (lane < 4) g_u[pos * 4 + lane] = expf(pre);
}

// ---------------------------------------------------------------------------
// K4: causal prefix sums per (b,h):
//   num[p,d] = sum_{q<=p} u[q]*enc[q,d]   (lane = d)
//   den[p]   = sum_{q<=p} u[q]
// Block per (b,h) (16 blocks), 8 warps x 256 positions; two-phase scan.
// ---------------------------------------------------------------------------
__global__ __launch_bounds__(256) void k4_scan()
{
    __shared__ float s_tn[8][32];
    __shared__ float s_td[8];

    int b = blockIdx.x >> 2, h = blockIdx.x & 3;
    int w = threadIdx.x >> 5, lane = threadIdx.x & 31;

    const float* up = g_u   + b * P_ * 4  + h;
    const float* ep = g_enc + b * P_ * 32 + lane;
    int pb = w * 256;

    float an = 0.0f, ad = 0.0f;
    for (int j = 0; j < 256; j++) {
        int p = pb + j;
        float uu = up[p * 4];
        an += uu * ep[p * 32];
        ad += uu;
    }
    s_tn[w][lane] = an;
    if (lane == 0) s_td[w] = ad;
    __syncthreads();

    float offn = 0.0f, offd = 0.0f;
    for (int w2 = 0; w2 < w; w2++) { offn += s_tn[w2][lane]; offd += s_td[w2]; }

    an = offn; ad = offd;
    float* np = g_num + (b * P_ * 4 + h) * 32 + lane;
    float* dp = g_den + b * P_ * 4 + h;
    for (int j = 0; j < 256; j++) {
        int p = pb + j;
        float uu = up[p * 4];
        an += uu * ep[p * 32];
        ad += uu;
        np[p * 128] = an;
        if (lane == 0) dp[p * 4] = ad;
    }
}

// ---------------------------------------------------------------------------
// K5: agg2 = (num/den) * mask * mask  (out5*mask, then x*mask inside rho MLP);
// rho: 128 -> 64 relu -> 64 relu; output * mask.
// One warp handles 4 positions (amortizes weight loads 4x). Lane = out ch
// j and j+32. Grid 256 blocks x 8 warps x 4 positions = 8192.
// ---------------------------------------------------------------------------
__global__ __launch_bounds__(256) void k5_rho(
    const float* __restrict__ mask,
    const float* __restrict__ rw1, const float* __restrict__ rb1,
    const float* __restrict__ rw2, const float* __restrict__ rb2,
    float* __restrict__ out)
{
    __shared__ float s_a[8][4][128];
    __shared__ float s_h[8][4][64];

    int w = threadIdx.x >> 5, lane = threadIdx.x & 31;
    int pos0 = (blockIdx.x * 8 + w) * 4;

    float mks[4];
    #pragma unroll
    for (int q = 0; q < 4; q++) {
        int pos = pos0 + q;
        float mk = mask[pos];
        mks[q] = mk;
        #pragma unroll
        for (int h = 0; h < 4; h++) {
            float den = g_den[pos * 4 + h];
            float nm  = g_num[(pos * 4 + h) * 32 + lane];
            s_a[w][q][h * 32 + lane] = nm / den * mk * mk;
        }
    }
    __syncwarp();

    float acc0[4], acc1[4];
    #pragma unroll
    for (int q = 0; q < 4; q++) { acc0[q] = rb1[lane]; acc1[q] = rb1[lane + 32]; }

    for (int k = 0; k < 128; k++) {
        float w0 = rw1[k * 64 + lane];
        float w1 = rw1[k * 64 + lane + 32];
        #pragma unroll
        for (int q = 0; q < 4; q++) {
            float a = s_a[w][q][k];
            acc0[q] += a * w0;
            acc1[q] += a * w1;
        }
    }
    #pragma unroll
    for (int q = 0; q < 4; q++) {
        s_h[w][q][lane]      = fmaxf(acc0[q], 0.0f) * mks[q];
        s_h[w][q][lane + 32] = fmaxf(acc1[q], 0.0f) * mks[q];
    }
    __syncwarp();

    #pragma unroll
    for (int q = 0; q < 4; q++) { acc0[q] = rb2[lane]; acc1[q] = rb2[lane + 32]; }

    for (int k = 0; k < 64; k++) {
        float w0 = rw2[k * 64 + lane];
        float w1 = rw2[k * 64 + lane + 32];
        #pragma unroll
        for (int q = 0; q < 4; q++) {
            float a = s_h[w][q][k];
            acc0[q] += a * w0;
            acc1[q] += a * w1;
        }
    }
    #pragma unroll
    for (int q = 0; q < 4; q++) {
        int pos = pos0 + q;
        out[pos * 64 + lane]      = fmaxf(acc0[q], 0.0f) * mks[q];
        out[pos * 64 + lane + 32] = fmaxf(acc1[q], 0.0f) * mks[q];
    }
}

// ---------------------------------------------------------------------------
extern "C" void kernel_launch(void* const* d_in, const int* in_sizes, int n_in,
                              void* d_out, int out_size)
{
    const float* times   = (const float*)d_in[0];
    const float* values  = (const float*)d_in[1];
    const int*   meas    = (const int*)  d_in[2];
    const float* mask    = (const float*)d_in[3];
    const float* psi_w1  = (const float*)d_in[4];
    const float* psi_b1  = (const float*)d_in[5];
    const float* psi_w2  = (const float*)d_in[6];
    const float* psi_b2  = (const float*)d_in[7];
    const float* arho_w  = (const float*)d_in[8];
    const float* arho_b  = (const float*)d_in[9];
    const float* W_k     = (const float*)d_in[10];
    const float* W_q     = (const float*)d_in[11];
    const float* phi_w1  = (const float*)d_in[12];
    const float* phi_b1  = (const float*)d_in[13];
    const float* phi_w2  = (const float*)d_in[14];
    const float* phi_b2  = (const float*)d_in[15];
    const float* rho_w1  = (const float*)d_in[16];
    const float* rho_b1  = (const float*)d_in[17];
    const float* rho_w2  = (const float*)d_in[18];
    const float* rho_b2  = (const float*)d_in[19];
    float* out = (float*)d_out;

    k1_feat_mlps<<<NPOS / 8, 256>>>(times, values, meas, mask,
                                    psi_w1, psi_b1, psi_w2, psi_b2,
                                    phi_w1, phi_b1, phi_w2, phi_b2);
    k2_cummean<<<16, 256>>>(mask);
    k3_preattn<<<NPOS / 8, 256>>>(times, values, meas, mask,
                                  arho_w, arho_b, W_k, W_q);
    k4_scan<<<16, 256>>>();
    k5_rho<<<256, 256>>>(mask, rho_w1, rho_b1, rho_w2, rho_b2, out);
}

// round 5
// speedup vs baseline: 1.4510x; 1.3672x over previous
#include <cuda_runtime.h>
#include <math.h>

#define FULL 0xffffffffu

// Problem constants
constexpr int B_ = 4;
constexpr int P_ = 2048;
constexpr int NPOS = B_ * P_;           // 8192

// Scratch (device globals; no allocation in kernel_launch)
__device__ float g_enc_psi[NPOS * 32];
__device__ float g_enc[NPOS * 32];
__device__ float g_aggraw[NPOS * 32];
__device__ float g_u[NPOS * 4];
__device__ float g_num[NPOS * 4 * 32];
__device__ float g_den[NPOS * 4];

// combined[lane] for one position:
//  lanes 0..7 : time encoding sin/cos with divisors 1,1,10,10,100,100,1000,1000
//  lane  8    : value
//  lanes 9..30: one-hot of measurement classes 1..22
__device__ __forceinline__ float combined_lane(float t, float v, int m, int lane) {
    if (lane < 8) {
        float sc;
        switch (lane >> 1) {
            case 0:  sc = 1.0f;   break;
            case 1:  sc = 0.1f;   break;
            case 2:  sc = 0.01f;  break;
            default: sc = 0.001f; break;
        }
        float r = t * sc;
        return (lane & 1) ? cosf(r) : sinf(r);
    } else if (lane == 8) {
        return v;
    } else if (lane < 31) {
        return (m == lane - 8) ? 1.0f : 0.0f;
    }
    return 0.0f;
}

// ---------------------------------------------------------------------------
// K1: per-position features + psi MLP + phi MLP.
// One warp per position; lane = hidden channel (32). Weights staged in smem.
// ---------------------------------------------------------------------------
__global__ __launch_bounds__(256) void k1_feat_mlps(
    const float* __restrict__ times, const float* __restrict__ values,
    const int* __restrict__ meas, const float* __restrict__ mask,
    const float* __restrict__ pw1, const float* __restrict__ pb1,
    const float* __restrict__ pw2, const float* __restrict__ pb2,
    const float* __restrict__ fw1, const float* __restrict__ fb1,
    const float* __restrict__ fw2, const float* __restrict__ fb2)
{
    __shared__ float s_pw1[31 * 32], s_pw2[32 * 32];
    __shared__ float s_fw1[31 * 32], s_fw2[32 * 32];
    __shared__ float s_pb1[32], s_pb2[32], s_fb1[32], s_fb2[32];

    int tid = threadIdx.x;
    for (int i = tid; i < 31 * 32; i += 256) { s_pw1[i] = pw1[i]; s_fw1[i] = fw1[i]; }
    for (int i = tid; i < 32 * 32; i += 256) { s_pw2[i] = pw2[i]; s_fw2[i] = fw2[i]; }
    if (tid < 32) { s_pb1[tid] = pb1[tid]; s_pb2[tid] = pb2[tid];
                    s_fb1[tid] = fb1[tid]; s_fb2[tid] = fb2[tid]; }
    __syncthreads();

    int lane = tid & 31;
    int pos  = blockIdx.x * 8 + (tid >> 5);   // grid = 1024 blocks -> 8192 positions

    float t  = times[pos];
    float v  = values[pos];
    float mk = mask[pos];
    int   m  = meas[pos];

    float xm = combined_lane(t, v, m, lane) * mk;   // (x * mask)

    // psi: h1 = relu(xm @ w1 + b1); h2 = relu(h1*mask @ w2 + b2); out = h2*mask
    float a = s_pb1[lane];
    #pragma unroll
    for (int i = 0; i < 31; i++)
        a += __shfl_sync(FULL, xm, i) * s_pw1[i * 32 + lane];
    float h = fmaxf(a, 0.0f) * mk;
    a = s_pb2[lane];
    #pragma unroll
    for (int k = 0; k < 32; k++)
        a += __shfl_sync(FULL, h, k) * s_pw2[k * 32 + lane];
    g_enc_psi[pos * 32 + lane] = fmaxf(a, 0.0f) * mk;

    // phi (same structure)
    a = s_fb1[lane];
    #pragma unroll
    for (int i = 0; i < 31; i++)
        a += __shfl_sync(FULL, xm, i) * s_fw1[i * 32 + lane];
    h = fmaxf(a, 0.0f) * mk;
    a = s_fb2[lane];
    #pragma unroll
    for (int k = 0; k < 32; k++)
        a += __shfl_sync(FULL, h, k) * s_fw2[k * 32 + lane];
    g_enc[pos * 32 + lane] = fmaxf(a, 0.0f) * mk;
}

// ---------------------------------------------------------------------------
// K2 v2: cumulative mean of enc_psi over P per (batch, channel).
// One warp per (b,c) = 128 warps; lane owns 64 consecutive positions held in
// REGISTERS: load once, 4-acc partial sum, warp exclusive scan, register-only
// write pass (no reloads in the dependent chain).
// ---------------------------------------------------------------------------
__global__ __launch_bounds__(256) void k2_cummean(const float* __restrict__ mask)
{
    int tid  = threadIdx.x;
    int lane = tid & 31;
    int w    = blockIdx.x * 8 + (tid >> 5);
    int b = w >> 5, c = w & 31;

    const float* src  = g_enc_psi + b * P_ * 32 + c;
    float*       dst  = g_aggraw  + b * P_ * 32 + c;
    const float* mptr = mask + b * P_;

    int p0 = lane * 64;

    float vals[64];
    #pragma unroll
    for (int j = 0; j < 64; j++) vals[j] = src[(p0 + j) * 32];

    float s0 = 0.f, s1 = 0.f, s2 = 0.f, s3 = 0.f;
    #pragma unroll
    for (int j = 0; j < 64; j += 4) {
        s0 += vals[j]; s1 += vals[j + 1]; s2 += vals[j + 2]; s3 += vals[j + 3];
    }
    float s = (s0 + s1) + (s2 + s3);

    // inclusive warp scan -> exclusive
    float run = s;
    #pragma unroll
    for (int off = 1; off < 32; off <<= 1) {
        float tpart = __shfl_up_sync(FULL, run, off);
        if (lane >= off) run += tpart;
    }
    float acc = run - s;

    #pragma unroll
    for (int j = 0; j < 64; j++) {
        int p = p0 + j;
        acc += vals[j];
        dst[p * 32] = __fdividef(acc, (float)(p + 1)) * mptr[p];
    }
}

// ---------------------------------------------------------------------------
// K3: agg = (agg_raw @ arho + b)*mask; keys = [combined, agg] @ W_k * mask;
// preattn[h] = sum_d keys[d*4+h]*W_q[h,d] / 4 * mask;  u = exp(preattn).
// One warp per position; lane j computes keys j and j+32.
// ---------------------------------------------------------------------------
__global__ __launch_bounds__(256) void k3_preattn(
    const float* __restrict__ times, const float* __restrict__ values,
    const int* __restrict__ meas, const float* __restrict__ mask,
    const float* __restrict__ arw, const float* __restrict__ arb,
    const float* __restrict__ wk, const float* __restrict__ wq)
{
    __shared__ float s_ar[32 * 32], s_wk[63 * 64];
    __shared__ float s_ab[32], s_wq[64];

    int tid = threadIdx.x;
    for (int i = tid; i < 32 * 32; i += 256) s_ar[i] = arw[i];
    for (int i = tid; i < 63 * 64; i += 256) s_wk[i] = wk[i];
    if (tid < 32) s_ab[tid] = arb[tid];
    if (tid < 64) s_wq[tid] = wq[tid];
    __syncthreads();

    int lane = tid & 31;
    int pos  = blockIdx.x * 8 + (tid >> 5);

    float t  = times[pos];
    float v  = values[pos];
    float mk = mask[pos];
    int   m  = meas[pos];

    float x  = combined_lane(t, v, m, lane);   // RAW combined (no mask) feeds W_k
    float ar = g_aggraw[pos * 32 + lane];

    float agg = s_ab[lane];
    #pragma unroll
    for (int k = 0; k < 32; k++)
        agg += __shfl_sync(FULL, ar, k) * s_ar[k * 32 + lane];
    agg *= mk;

    float a0 = 0.0f, a1 = 0.0f;
    #pragma unroll
    for (int i = 0; i < 31; i++) {
        float c = __shfl_sync(FULL, x, i);
        a0 += c * s_wk[i * 64 + lane];
        a1 += c * s_wk[i * 64 + lane + 32];
    }
    #pragma unroll
    for (int c = 0; c < 32; c++) {
        float g = __shfl_sync(FULL, agg, c);
        a0 += g * s_wk[(31 + c) * 64 + lane];
        a1 += g * s_wk[(31 + c) * 64 + lane + 32];
    }
    a0 *= mk; a1 *= mk;   // keys * mask

    // keys flat index k = d*4 + h : lane -> (h=lane&3, d=lane>>2); lane+32 -> same h, d+8
    int hh = lane & 3, dd = lane >> 2;
    float part = a0 * s_wq[hh * 16 + dd] + a1 * s_wq[hh * 16 + dd + 8];
    part += __shfl_xor_sync(FULL, part, 4);
    part += __shfl_xor_sync(FULL, part, 8);
    part += __shfl_xor_sync(FULL, part, 16);

    float pre = part * 0.25f * mk;   // / sqrt(16), then * mask
    if (lane < 4) g_u[pos * 4 + lane] = expf(pre);
}

// ---------------------------------------------------------------------------
// K4 v2: causal prefix sums, one WARP per (b, h, channel):
//   c in [0,32): num[p,c] = sum_{q<=p} u[q]*enc[q,c]
//   c == 32   : den[p]   = sum_{q<=p} u[q]
// 4*4*33 = 528 warps = 66 blocks x 8 warps. Lane owns 64 consecutive
// positions, values register-resident: load once -> partial sum -> warp
// exclusive scan -> register-only sequential write pass.
// ---------------------------------------------------------------------------
__global__ __launch_bounds__(256) void k4_scan()
{
    int tid  = threadIdx.x;
    int lane = tid & 31;
    int wg   = blockIdx.x * 8 + (tid >> 5);    // 0..527
    int b    = wg / 132;
    int rem  = wg - b * 132;
    int h    = rem / 33;
    int c    = rem - h * 33;

    const float* up = g_u + b * P_ * 4 + h;
    int p0 = lane * 64;

    float vals[64];
    if (c < 32) {
        const float* ep = g_enc + b * P_ * 32 + c;
        #pragma unroll
        for (int j = 0; j < 64; j++) {
            int p = p0 + j;
            vals[j] = up[p * 4] * ep[p * 32];
        }
    } else {
        #pragma unroll
        for (int j = 0; j < 64; j++) vals[j] = up[(p0 + j) * 4];
    }

    float s0 = 0.f, s1 = 0.f, s2 = 0.f, s3 = 0.f;
    #pragma unroll
    for (int j = 0; j < 64; j += 4) {
        s0 += vals[j]; s1 += vals[j + 1]; s2 += vals[j + 2]; s3 += vals[j + 3];
    }
    float s = (s0 + s1) + (s2 + s3);

    // inclusive warp scan -> exclusive offset
    float run = s;
    #pragma unroll
    for (int off = 1; off < 32; off <<= 1) {
        float tpart = __shfl_up_sync(FULL, run, off);
        if (lane >= off) run += tpart;
    }
    float acc = run - s;

    if (c < 32) {
        float* np = g_num + (b * P_ * 4 + h) * 32 + c;
        #pragma unroll
        for (int j = 0; j < 64; j++) {
            acc += vals[j];
            np[(p0 + j) * 128] = acc;
        }
    } else {
        float* dp = g_den + b * P_ * 4 + h;
        #pragma unroll
        for (int j = 0; j < 64; j++) {
            acc += vals[j];
            dp[(p0 + j) * 4] = acc;
        }
    }
}

// ---------------------------------------------------------------------------
// K5: agg2 = (num/den) * mask * mask  (out5*mask, then x*mask inside rho MLP);
// rho: 128 -> 64 relu -> 64 relu; output * mask.
// One warp handles 4 positions (amortizes weight loads 4x). Lane = out ch
// j and j+32. Grid 256 blocks x 8 warps x 4 positions = 8192.
// ---------------------------------------------------------------------------
__global__ __launch_bounds__(256) void k5_rho(
    const float* __restrict__ mask,
    const float* __restrict__ rw1, const float* __restrict__ rb1,
    const float* __restrict__ rw2, const float* __restrict__ rb2,
    float* __restrict__ out)
{
    __shared__ float s_a[8][4][128];
    __shared__ float s_h[8][4][64];

    int w = threadIdx.x >> 5, lane = threadIdx.x & 31;
    int pos0 = (blockIdx.x * 8 + w) * 4;

    float mks[4];
    #pragma unroll
    for (int q = 0; q < 4; q++) {
        int pos = pos0 + q;
        float mk = mask[pos];
        mks[q] = mk;
        #pragma unroll
        for (int h = 0; h < 4; h++) {
            float den = g_den[pos * 4 + h];
            float nm  = g_num[(pos * 4 + h) * 32 + lane];
            s_a[w][q][h * 32 + lane] = nm / den * mk * mk;
        }
    }
    __syncwarp();

    float acc0[4], acc1[4];
    #pragma unroll
    for (int q = 0; q < 4; q++) { acc0[q] = rb1[lane]; acc1[q] = rb1[lane + 32]; }

    for (int k = 0; k < 128; k++) {
        float w0 = rw1[k * 64 + lane];
        float w1 = rw1[k * 64 + lane + 32];
        #pragma unroll
        for (int q = 0; q < 4; q++) {
            float a = s_a[w][q][k];
            acc0[q] += a * w0;
            acc1[q] += a * w1;
        }
    }
    #pragma unroll
    for (int q = 0; q < 4; q++) {
        s_h[w][q][lane]      = fmaxf(acc0[q], 0.0f) * mks[q];
        s_h[w][q][lane + 32] = fmaxf(acc1[q], 0.0f) * mks[q];
    }
    __syncwarp();

    #pragma unroll
    for (int q = 0; q < 4; q++) { acc0[q] = rb2[lane]; acc1[q] = rb2[lane + 32]; }

    for (int k = 0; k < 64; k++) {
        float w0 = rw2[k * 64 + lane];
        float w1 = rw2[k * 64 + lane + 32];
        #pragma unroll
        for (int q = 0; q < 4; q++) {
            float a = s_h[w][q][k];
            acc0[q] += a * w0;
            acc1[q] += a * w1;
        }
    }
    #pragma unroll
    for (int q = 0; q < 4; q++) {
        int pos = pos0 + q;
        out[pos * 64 + lane]      = fmaxf(acc0[q], 0.0f) * mks[q];
        out[pos * 64 + lane + 32] = fmaxf(acc1[q], 0.0f) * mks[q];
    }
}

// ---------------------------------------------------------------------------
extern "C" void kernel_launch(void* const* d_in, const int* in_sizes, int n_in,
                              void* d_out, int out_size)
{
    const float* times   = (const float*)d_in[0];
    const float* values  = (const float*)d_in[1];
    const int*   meas    = (const int*)  d_in[2];
    const float* mask    = (const float*)d_in[3];
    const float* psi_w1  = (const float*)d_in[4];
    const float* psi_b1  = (const float*)d_in[5];
    const float* psi_w2  = (const float*)d_in[6];
    const float* psi_b2  = (const float*)d_in[7];
    const float* arho_w  = (const float*)d_in[8];
    const float* arho_b  = (const float*)d_in[9];
    const float* W_k     = (const float*)d_in[10];
    const float* W_q     = (const float*)d_in[11];
    const float* phi_w1  = (const float*)d_in[12];
    const float* phi_b1  = (const float*)d_in[13];
    const float* phi_w2  = (const float*)d_in[14];
    const float* phi_b2  = (const float*)d_in[15];
    const float* rho_w1  = (const float*)d_in[16];
    const float* rho_b1  = (const float*)d_in[17];
    const float* rho_w2  = (const float*)d_in[18];
    const float* rho_b2  = (const float*)d_in[19];
    float* out = (float*)d_out;

    k1_feat_mlps<<<NPOS / 8, 256>>>(times, values, meas, mask,
                                    psi_w1, psi_b1, psi_w2, psi_b2,
                                    phi_w1, phi_b1, phi_w2, phi_b2);
    k2_cummean<<<16, 256>>>(mask);
    k3_preattn<<<NPOS / 8, 256>>>(times, values, meas, mask,
                                  arho_w, arho_b, W_k, W_q);
    k4_scan<<<66, 256>>>();
    k5_rho<<<256, 256>>>(mask, rho_w1, rho_b1, rho_w2, rho_b2, out);
}

// round 6
// speedup vs baseline: 2.8282x; 1.9492x over previous
#include <cuda_runtime.h>
#include <math.h>

#define FULL 0xffffffffu
typedef unsigned long long ull;

// Problem constants
constexpr int B_ = 4;
constexpr int P_ = 2048;
constexpr int NPOS = B_ * P_;           // 8192

// Scratch (device globals; no allocation in kernel_launch)
__device__ float g_enc_psi[NPOS * 32];
__device__ float g_enc[NPOS * 32];
__device__ float g_aggraw[NPOS * 32];
__device__ float g_u[NPOS * 4];
__device__ float g_num[NPOS * 4 * 32];
__device__ float g_den[NPOS * 4];

// ---- f32x2 packed helpers (sm_103a FFMA2 path) ------------------------------
__device__ __forceinline__ ull pack2(float x, float y) {
    ull r; asm("mov.b64 %0, {%1, %2};" : "=l"(r) : "f"(x), "f"(y)); return r;
}
__device__ __forceinline__ void unpack2(ull v, float& x, float& y) {
    asm("mov.b64 {%0, %1}, %2;" : "=f"(x), "=f"(y) : "l"(v));
}
__device__ __forceinline__ ull ffma2(ull a, ull b, ull c) {
    ull d; asm("fma.rn.f32x2 %0, %1, %2, %3;" : "=l"(d) : "l"(a), "l"(b), "l"(c));
    return d;
}

// combined[lane] for one position:
//  lanes 0..7 : time encoding sin/cos with divisors 1,1,10,10,100,100,1000,1000
//  lane  8    : value
//  lanes 9..30: one-hot of measurement classes 1..22
__device__ __forceinline__ float combined_lane(float t, float v, int m, int lane) {
    if (lane < 8) {
        float sc;
        switch (lane >> 1) {
            case 0:  sc = 1.0f;   break;
            case 1:  sc = 0.1f;   break;
            case 2:  sc = 0.01f;  break;
            default: sc = 0.001f; break;
        }
        float r = t * sc;
        return (lane & 1) ? cosf(r) : sinf(r);
    } else if (lane == 8) {
        return v;
    } else if (lane < 31) {
        return (m == lane - 8) ? 1.0f : 0.0f;
    }
    return 0.0f;
}

// ---------------------------------------------------------------------------
// K1: per-position features + psi MLP + phi MLP.
// Grid 256 x 256 threads; each warp processes 4 positions (amortizes smem
// weight fill 4x and gives 4-way ILP on the dependent dot-product chains).
// ---------------------------------------------------------------------------
__global__ __launch_bounds__(256) void k1_feat_mlps(
    const float* __restrict__ times, const float* __restrict__ values,
    const int* __restrict__ meas, const float* __restrict__ mask,
    const float* __restrict__ pw1, const float* __restrict__ pb1,
    const float* __restrict__ pw2, const float* __restrict__ pb2,
    const float* __restrict__ fw1, const float* __restrict__ fb1,
    const float* __restrict__ fw2, const float* __restrict__ fb2)
{
    __shared__ float s_pw1[31 * 32], s_pw2[32 * 32];
    __shared__ float s_fw1[31 * 32], s_fw2[32 * 32];
    __shared__ float s_pb1[32], s_pb2[32], s_fb1[32], s_fb2[32];

    int tid = threadIdx.x;
    for (int i = tid; i < 31 * 32; i += 256) { s_pw1[i] = pw1[i]; s_fw1[i] = fw1[i]; }
    for (int i = tid; i < 32 * 32; i += 256) { s_pw2[i] = pw2[i]; s_fw2[i] = fw2[i]; }
    if (tid < 32) { s_pb1[tid] = pb1[tid]; s_pb2[tid] = pb2[tid];
                    s_fb1[tid] = fb1[tid]; s_fb2[tid] = fb2[tid]; }
    __syncthreads();

    int lane = tid & 31;
    int w    = tid >> 5;
    int pos0 = (blockIdx.x * 8 + w) * 4;

    float xm[4], mk[4];
    #pragma unroll
    for (int q = 0; q < 4; q++) {
        int pos = pos0 + q;
        float t = times[pos], v = values[pos];
        mk[q] = mask[pos];
        int m = meas[pos];
        xm[q] = combined_lane(t, v, m, lane) * mk[q];
    }

    float a[4], h[4];

    // psi
    #pragma unroll
    for (int q = 0; q < 4; q++) a[q] = s_pb1[lane];
    #pragma unroll
    for (int i = 0; i < 31; i++) {
        float wv = s_pw1[i * 32 + lane];
        #pragma unroll
        for (int q = 0; q < 4; q++) a[q] += __shfl_sync(FULL, xm[q], i) * wv;
    }
    #pragma unroll
    for (int q = 0; q < 4; q++) h[q] = fmaxf(a[q], 0.0f) * mk[q];
    #pragma unroll
    for (int q = 0; q < 4; q++) a[q] = s_pb2[lane];
    #pragma unroll
    for (int k = 0; k < 32; k++) {
        float wv = s_pw2[k * 32 + lane];
        #pragma unroll
        for (int q = 0; q < 4; q++) a[q] += __shfl_sync(FULL, h[q], k) * wv;
    }
    #pragma unroll
    for (int q = 0; q < 4; q++)
        g_enc_psi[(pos0 + q) * 32 + lane] = fmaxf(a[q], 0.0f) * mk[q];

    // phi
    #pragma unroll
    for (int q = 0; q < 4; q++) a[q] = s_fb1[lane];
    #pragma unroll
    for (int i = 0; i < 31; i++) {
        float wv = s_fw1[i * 32 + lane];
        #pragma unroll
        for (int q = 0; q < 4; q++) a[q] += __shfl_sync(FULL, xm[q], i) * wv;
    }
    #pragma unroll
    for (int q = 0; q < 4; q++) h[q] = fmaxf(a[q], 0.0f) * mk[q];
    #pragma unroll
    for (int q = 0; q < 4; q++) a[q] = s_fb2[lane];
    #pragma unroll
    for (int k = 0; k < 32; k++) {
        float wv = s_fw2[k * 32 + lane];
        #pragma unroll
        for (int q = 0; q < 4; q++) a[q] += __shfl_sync(FULL, h[q], k) * wv;
    }
    #pragma unroll
    for (int q = 0; q < 4; q++)
        g_enc[(pos0 + q) * 32 + lane] = fmaxf(a[q], 0.0f) * mk[q];
}

// ---------------------------------------------------------------------------
// K2 v3: cumulative mean, COALESCED (lane = channel).
// Grid 8 = (b, half) x 512 threads (16 warps). Warp w owns chunk
// ch = half*16+w (64 positions), values register-resident & every access 1
// wavefront. Second-half blocks stream first-half chunk totals (warp w streams
// chunk w). Block-level smem combine gives exclusive offsets.
// ---------------------------------------------------------------------------
__global__ __launch_bounds__(512) void k2_cummean(const float* __restrict__ mask)
{
    __shared__ float s_pre[16][32], s_tot[16][32];
    __shared__ float s_rcp[2048];

    int tid  = threadIdx.x;
    int lane = tid & 31;
    int w    = tid >> 5;                   // 0..15
    int b    = blockIdx.x >> 1;
    int half = blockIdx.x & 1;

    for (int i = tid; i < 2048; i += 512) s_rcp[i] = 1.0f / (float)(i + 1);

    const float* src  = g_enc_psi + b * P_ * 32 + lane;
    float*       dst  = g_aggraw  + b * P_ * 32 + lane;
    const float* mptr = mask + b * P_;

    // Stream first-half chunk totals (second-half blocks only)
    if (half) {
        int sp = w * 64;
        float t0 = 0.f, t1 = 0.f, t2 = 0.f, t3 = 0.f;
        #pragma unroll 4
        for (int j = 0; j < 64; j += 4) {
            t0 += src[(sp + j) * 32];     t1 += src[(sp + j + 1) * 32];
            t2 += src[(sp + j + 2) * 32]; t3 += src[(sp + j + 3) * 32];
        }
        s_pre[w][lane] = (t0 + t1) + (t2 + t3);
    }

    // Own chunk, register resident
    int ch = half * 16 + w;
    int p0 = ch * 64;
    float vals[64];
    #pragma unroll
    for (int j = 0; j < 64; j++) vals[j] = src[(p0 + j) * 32];

    float t0 = 0.f, t1 = 0.f, t2 = 0.f, t3 = 0.f;
    #pragma unroll
    for (int j = 0; j < 64; j += 4) {
        t0 += vals[j]; t1 += vals[j + 1]; t2 += vals[j + 2]; t3 += vals[j + 3];
    }
    s_tot[w][lane] = (t0 + t1) + (t2 + t3);
    __syncthreads();

    float off = 0.0f;
    if (half) {
        #pragma unroll
        for (int k = 0; k < 16; k++) off += s_pre[k][lane];
    }
    for (int k = 0; k < w; k++) off += s_tot[k][lane];

    float acc = off;
    #pragma unroll
    for (int j = 0; j < 64; j++) {
        int p = p0 + j;
        acc += vals[j];
        dst[p * 32] = acc * s_rcp[p] * mptr[p];
    }
}

// ---------------------------------------------------------------------------
// K3: agg = (agg_raw @ arho + b)*mask; keys = [combined, agg] @ W_k * mask;
// preattn -> u = exp(preattn). Each warp processes 4 positions (amortized
// 20KB smem fill + 4-way ILP). Grid 256 x 256 threads.
// ---------------------------------------------------------------------------
__global__ __launch_bounds__(256) void k3_preattn(
    const float* __restrict__ times, const float* __restrict__ values,
    const int* __restrict__ meas, const float* __restrict__ mask,
    const float* __restrict__ arw, const float* __restrict__ arb,
    const float* __restrict__ wk, const float* __restrict__ wq)
{
    __shared__ float s_ar[32 * 32], s_wk[63 * 64];
    __shared__ float s_ab[32], s_wq[64];

    int tid = threadIdx.x;
    for (int i = tid; i < 32 * 32; i += 256) s_ar[i] = arw[i];
    for (int i = tid; i < 63 * 64; i += 256) s_wk[i] = wk[i];
    if (tid < 32) s_ab[tid] = arb[tid];
    if (tid < 64) s_wq[tid] = wq[tid];
    __syncthreads();

    int lane = tid & 31;
    int w    = tid >> 5;
    int pos0 = (blockIdx.x * 8 + w) * 4;

    float x[4], ar[4], mk[4];
    #pragma unroll
    for (int q = 0; q < 4; q++) {
        int pos = pos0 + q;
        float t = times[pos], v = values[pos];
        mk[q] = mask[pos];
        int m = meas[pos];
        x[q]  = combined_lane(t, v, m, lane);       // RAW combined feeds W_k
        ar[q] = g_aggraw[pos * 32 + lane];
    }

    float agg[4];
    #pragma unroll
    for (int q = 0; q < 4; q++) agg[q] = s_ab[lane];
    #pragma unroll
    for (int k = 0; k < 32; k++) {
        float wv = s_ar[k * 32 + lane];
        #pragma unroll
        for (int q = 0; q < 4; q++) agg[q] += __shfl_sync(FULL, ar[q], k) * wv;
    }
    #pragma unroll
    for (int q = 0; q < 4; q++) agg[q] *= mk[q];

    float a0[4] = {0.f, 0.f, 0.f, 0.f}, a1[4] = {0.f, 0.f, 0.f, 0.f};
    #pragma unroll
    for (int i = 0; i < 31; i++) {
        float w0 = s_wk[i * 64 + lane];
        float w1 = s_wk[i * 64 + lane + 32];
        #pragma unroll
        for (int q = 0; q < 4; q++) {
            float c = __shfl_sync(FULL, x[q], i);
            a0[q] += c * w0; a1[q] += c * w1;
        }
    }
    #pragma unroll
    for (int c = 0; c < 32; c++) {
        float w0 = s_wk[(31 + c) * 64 + lane];
        float w1 = s_wk[(31 + c) * 64 + lane + 32];
        #pragma unroll
        for (int q = 0; q < 4; q++) {
            float g = __shfl_sync(FULL, agg[q], c);
            a0[q] += g * w0; a1[q] += g * w1;
        }
    }

    int hh = lane & 3, dd = lane >> 2;
    float q0 = s_wq[hh * 16 + dd], q1 = s_wq[hh * 16 + dd + 8];
    #pragma unroll
    for (int q = 0; q < 4; q++) {
        float part = a0[q] * mk[q] * q0 + a1[q] * mk[q] * q1;
        part += __shfl_xor_sync(FULL, part, 4);
        part += __shfl_xor_sync(FULL, part, 8);
        part += __shfl_xor_sync(FULL, part, 16);
        float pre = part * 0.25f * mk[q];
        if (lane < 4) g_u[(pos0 + q) * 4 + lane] = expf(pre);
    }
}

// ---------------------------------------------------------------------------
// K4 v3: causal prefix sums, COALESCED (lane = channel), den folded in.
// Grid 32 = (b,h) x half; 512 threads (16 warps). Warp w owns chunk
// ch = half*16+w (64 positions): enc loads are 1 wavefront/line, u loads are
// broadcast. Second-half blocks stream first-half chunk totals. Write pass
// is a register-only FFMA chain.
// ---------------------------------------------------------------------------
__global__ __launch_bounds__(512) void k4_scan()
{
    __shared__ float s_pre[16][32], s_tot[16][32];
    __shared__ float s_preu[16], s_totu[16];

    int tid  = threadIdx.x;
    int lane = tid & 31;
    int w    = tid >> 5;                 // 0..15
    int bh   = blockIdx.x >> 1;
    int half = blockIdx.x & 1;
    int b    = bh >> 2, h = bh & 3;

    const float* up = g_u   + b * P_ * 4 + h;     // up[p*4]
    const float* ep = g_enc + b * P_ * 32 + lane; // ep[p*32]

    if (half) {
        int sp = w * 64;
        float t0 = 0.f, t1 = 0.f, t2 = 0.f, t3 = 0.f;
        float u0 = 0.f, u1 = 0.f, u2 = 0.f, u3 = 0.f;
        #pragma unroll 4
        for (int j = 0; j < 64; j += 4) {
            float ua = up[(sp + j) * 4],     ub = up[(sp + j + 1) * 4];
            float uc = up[(sp + j + 2) * 4], ud = up[(sp + j + 3) * 4];
            t0 += ua * ep[(sp + j) * 32];     t1 += ub * ep[(sp + j + 1) * 32];
            t2 += uc * ep[(sp + j + 2) * 32]; t3 += ud * ep[(sp + j + 3) * 32];
            u0 += ua; u1 += ub; u2 += uc; u3 += ud;
        }
        s_pre[w][lane] = (t0 + t1) + (t2 + t3);
        if (lane == 0) s_preu[w] = (u0 + u1) + (u2 + u3);
    }

    int ch = half * 16 + w;
    int p0 = ch * 64;
    float vals[64];
    {
        float u0 = 0.f, u1 = 0.f, u2 = 0.f, u3 = 0.f;
        #pragma unroll
        for (int j = 0; j < 64; j += 4) {
            float ua = up[(p0 + j) * 4],     ub = up[(p0 + j + 1) * 4];
            float uc = up[(p0 + j + 2) * 4], ud = up[(p0 + j + 3) * 4];
            vals[j]     = ua * ep[(p0 + j) * 32];
            vals[j + 1] = ub * ep[(p0 + j + 1) * 32];
            vals[j + 2] = uc * ep[(p0 + j + 2) * 32];
            vals[j + 3] = ud * ep[(p0 + j + 3) * 32];
            u0 += ua; u1 += ub; u2 += uc; u3 += ud;
        }
        float t0 = 0.f, t1 = 0.f, t2 = 0.f, t3 = 0.f;
        #pragma unroll
        for (int j = 0; j < 64; j += 4) {
            t0 += vals[j]; t1 += vals[j + 1]; t2 += vals[j + 2]; t3 += vals[j + 3];
        }
        s_tot[w][lane] = (t0 + t1) + (t2 + t3);
        if (lane == 0) s_totu[w] = (u0 + u1) + (u2 + u3);
    }
    __syncthreads();

    float offn = 0.0f, offu = 0.0f;
    if (half) {
        #pragma unroll
        for (int k = 0; k < 16; k++) { offn += s_pre[k][lane]; offu += s_preu[k]; }
    }
    for (int k = 0; k < w; k++) { offn += s_tot[k][lane]; offu += s_totu[k]; }

    float* nq = g_num + (b * P_ * 4 + h) * 32 + lane;  // nq[p*128]
    float* dq = g_den + b * P_ * 4 + h;                // dq[p*4]

    float accn = offn, accu = offu;
    #pragma unroll
    for (int j = 0; j < 64; j++) {
        int p = p0 + j;
        accn += vals[j];
        accu += up[p * 4];
        nq[p * 128] = accn;
        if (lane == 0) dq[p * 4] = accu;
    }
}

// ---------------------------------------------------------------------------
// K5 v2: rho MLP with packed f32x2 FFMA.
// Grid 128 x 256 threads (8 warps), each warp 8 positions. 144KB dynamic smem:
//   s_w1: 64 k-pairs x 32 lanes x float4 (w[k][l], w[k][l+32], w[k+1][l], w[k+1][l+32])
//   s_w2: 32 k-pairs x 32 x float4
//   s_a : [8 warps][8 q][128] duplicated (a,a) as ull  -> LDS.128 covers 2 k's
//   s_h : [8][8][64] duplicated
// Inner loop per k-pair: 1 LDS.128 (weights) + per q (1 LDS.128 + 2 FFMA2).
// ---------------------------------------------------------------------------
__global__ __launch_bounds__(256) void k5_rho(
    const float* __restrict__ mask,
    const float* __restrict__ rw1, const float* __restrict__ rb1,
    const float* __restrict__ rw2, const float* __restrict__ rb2,
    float* __restrict__ out)
{
    extern __shared__ char sm5[];
    float4* s_w1 = (float4*)sm5;                    // 2048 float4 = 32KB
    float4* s_w2 = (float4*)(sm5 + 32768);          // 1024 float4 = 16KB
    ull*    s_a  = (ull*)   (sm5 + 49152);          // 8192 ull    = 64KB
    ull*    s_h  = (ull*)   (sm5 + 114688);         // 4096 ull    = 32KB

    int tid = threadIdx.x;
    int w = tid >> 5, lane = tid & 31;

    // Pack weights: pair consecutive k's for LDS.128
    for (int i = tid; i < 2048; i += 256) {
        int kp = i >> 5, l = i & 31, k = kp * 2;
        s_w1[i] = make_float4(rw1[k * 64 + l],        rw1[k * 64 + l + 32],
                              rw1[(k + 1) * 64 + l],  rw1[(k + 1) * 64 + l + 32]);
    }
    for (int i = tid; i < 1024; i += 256) {
        int kp = i >> 5, l = i & 31, k = kp * 2;
        s_w2[i] = make_float4(rw2[k * 64 + l],        rw2[k * 64 + l + 32],
                              rw2[(k + 1) * 64 + l],  rw2[(k + 1) * 64 + l + 32]);
    }

    // Stage agg2 = num/den * mask^2, duplicated for f32x2
    int pos0 = (blockIdx.x * 8 + w) * 8;
    float mks[8];
    #pragma unroll
    for (int q = 0; q < 8; q++) {
        int pos = pos0 + q;
        float mk = mask[pos];
        mks[q] = mk;
        float mk2 = mk * mk;
        #pragma unroll
        for (int h4 = 0; h4 < 4; h4++) {
            float sc = __fdividef(mk2, g_den[pos * 4 + h4]);
            float v  = g_num[(pos * 4 + h4) * 32 + lane] * sc;
            s_a[(w * 8 + q) * 128 + h4 * 32 + lane] = pack2(v, v);
        }
    }
    __syncthreads();

    ull acc[8];
    {
        ull bini = pack2(rb1[lane], rb1[lane + 32]);
        #pragma unroll
        for (int q = 0; q < 8; q++) acc[q] = bini;
    }

    const ulonglong2* w1v = (const ulonglong2*)s_w1;
    const ulonglong2* av  = (const ulonglong2*)s_a;
    #pragma unroll 4
    for (int kp = 0; kp < 64; kp++) {
        ulonglong2 wv = w1v[kp * 32 + lane];
        #pragma unroll
        for (int q = 0; q < 8; q++) {
            ulonglong2 a2 = av[(w * 8 + q) * 64 + kp];
            acc[q] = ffma2(a2.x, wv.x, acc[q]);
            acc[q] = ffma2(a2.y, wv.y, acc[q]);
        }
    }

    #pragma unroll
    for (int q = 0; q < 8; q++) {
        float r0, r1; unpack2(acc[q], r0, r1);
        r0 = fmaxf(r0, 0.0f) * mks[q];
        r1 = fmaxf(r1, 0.0f) * mks[q];
        s_h[(w * 8 + q) * 64 + lane]      = pack2(r0, r0);
        s_h[(w * 8 + q) * 64 + lane + 32] = pack2(r1, r1);
    }
    __syncwarp();

    {
        ull bini = pack2(rb2[lane], rb2[lane + 32]);
        #pragma unroll
        for (int q = 0; q < 8; q++) acc[q] = bini;
    }

    const ulonglong2* w2v = (const ulonglong2*)s_w2;
    const ulonglong2* hv  = (const ulonglong2*)s_h;
    #pragma unroll 4
    for (int kp = 0; kp < 32; kp++) {
        ulonglong2 wv = w2v[kp * 32 + lane];
        #pragma unroll
        for (int q = 0; q < 8; q++) {
            ulonglong2 a2 = hv[(w * 8 + q) * 32 + kp];
            acc[q] = ffma2(a2.x, wv.x, acc[q]);
            acc[q] = ffma2(a2.y, wv.y, acc[q]);
        }
    }

    #pragma unroll
    for (int q = 0; q < 8; q++) {
        int pos = pos0 + q;
        float r0, r1; unpack2(acc[q], r0, r1);
        out[pos * 64 + lane]      = fmaxf(r0, 0.0f) * mks[q];
        out[pos * 64 + lane + 32] = fmaxf(r1, 0.0f) * mks[q];
    }
}

// ---------------------------------------------------------------------------
extern "C" void kernel_launch(void* const* d_in, const int* in_sizes, int n_in,
                              void* d_out, int out_size)
{
    const float* times   = (const float*)d_in[0];
    const float* values  = (const float*)d_in[1];
    const int*   meas    = (const int*)  d_in[2];
    const float* mask    = (const float*)d_in[3];
    const float* psi_w1  = (const float*)d_in[4];
    const float* psi_b1  = (const float*)d_in[5];
    const float* psi_w2  = (const float*)d_in[6];
    const float* psi_b2  = (const float*)d_in[7];
    const float* arho_w  = (const float*)d_in[8];
    const float* arho_b  = (const float*)d_in[9];
    const float* W_k     = (const float*)d_in[10];
    const float* W_q     = (const float*)d_in[11];
    const float* phi_w1  = (const float*)d_in[12];
    const float* phi_b1  = (const float*)d_in[13];
    const float* phi_w2  = (const float*)d_in[14];
    const float* phi_b2  = (const float*)d_in[15];
    const float* rho_w1  = (const float*)d_in[16];
    const float* rho_b1  = (const float*)d_in[17];
    const float* rho_w2  = (const float*)d_in[18];
    const float* rho_b2  = (const float*)d_in[19];
    float* out = (float*)d_out;

    static bool attr_done = false;
    cudaFuncSetAttribute(k5_rho, cudaFuncAttributeMaxDynamicSharedMemorySize, 147456);
    (void)attr_done;

    k1_feat_mlps<<<256, 256>>>(times, values, meas, mask,
                               psi_w1, psi_b1, psi_w2, psi_b2,
                               phi_w1, phi_b1, phi_w2, phi_b2);
    k2_cummean<<<8, 512>>>(mask);
    k3_preattn<<<256, 256>>>(times, values, meas, mask,
                             arho_w, arho_b, W_k, W_q);
    k4_scan<<<32, 512>>>();
    k5_rho<<<128, 256, 147456>>>(mask, rho_w1, rho_b1, rho_w2, rho_b2, out);
}

// round 7
// speedup vs baseline: 3.4796x; 1.2303x over previous
#include <cuda_runtime.h>
#include <math.h>

#define FULL 0xffffffffu
typedef unsigned long long ull;

// Problem constants
constexpr int B_ = 4;
constexpr int P_ = 2048;
constexpr int NPOS = B_ * P_;           // 8192

// Scratch (device globals; no allocation in kernel_launch)
__device__ float g_enc_psi[NPOS * 32];
__device__ float g_enc[NPOS * 32];
__device__ float g_aggraw[NPOS * 32];
__device__ float g_u[NPOS * 4];
__device__ float g_num[NPOS * 4 * 32];
__device__ float g_den[NPOS * 4];

// ---- f32x2 packed helpers (sm_103a FFMA2 path) ------------------------------
__device__ __forceinline__ ull pack2(float x, float y) {
    ull r; asm("mov.b64 %0, {%1, %2};" : "=l"(r) : "f"(x), "f"(y)); return r;
}
__device__ __forceinline__ void unpack2(ull v, float& x, float& y) {
    asm("mov.b64 {%0, %1}, %2;" : "=f"(x), "=f"(y) : "l"(v));
}
__device__ __forceinline__ ull ffma2(ull a, ull b, ull c) {
    ull d; asm("fma.rn.f32x2 %0, %1, %2, %3;" : "=l"(d) : "l"(a), "l"(b), "l"(c));
    return d;
}

// combined[lane] for one position:
//  lanes 0..7 : time encoding sin/cos with divisors 1,1,10,10,100,100,1000,1000
//  lane  8    : value
//  lanes 9..30: one-hot of measurement classes 1..22
//  lane  31   : 0 (pad)
__device__ __forceinline__ float combined_lane(float t, float v, int m, int lane) {
    if (lane < 8) {
        float sc;
        switch (lane >> 1) {
            case 0:  sc = 1.0f;   break;
            case 1:  sc = 0.1f;   break;
            case 2:  sc = 0.01f;  break;
            default: sc = 0.001f; break;
        }
        float r = t * sc;
        return (lane & 1) ? cosf(r) : sinf(r);
    } else if (lane == 8) {
        return v;
    } else if (lane < 31) {
        return (m == lane - 8) ? 1.0f : 0.0f;
    }
    return 0.0f;
}

// ---------------------------------------------------------------------------
// K1 v3: per-position features + psi MLP + phi MLP, LDS.128 broadcast style.
// Grid 256 x 256 threads; warp handles 4 positions. Inputs staged per-warp in
// smem; weights packed 4-rows-per-float4. Inner loop: LDS.128(w) +
// LDS.128(x, broadcast) + 4 FFMA per (i4, q).
// ---------------------------------------------------------------------------
__global__ __launch_bounds__(256) void k1_feat_mlps(
    const float* __restrict__ times, const float* __restrict__ values,
    const int* __restrict__ meas, const float* __restrict__ mask,
    const float* __restrict__ pw1, const float* __restrict__ pb1,
    const float* __restrict__ pw2, const float* __restrict__ pb2,
    const float* __restrict__ fw1, const float* __restrict__ fb1,
    const float* __restrict__ fw2, const float* __restrict__ fb2)
{
    __shared__ float4 s_pw1[8 * 32], s_pw2[8 * 32];
    __shared__ float4 s_fw1[8 * 32], s_fw2[8 * 32];
    __shared__ float  s_pb1[32], s_pb2[32], s_fb1[32], s_fb2[32];
    __shared__ float4 s_x4[8][4][8];     // staged input vectors (32 floats/pos)
    __shared__ float4 s_h4[8][4][8];     // staged hidden vectors

    int tid = threadIdx.x;
    // Pack weight rows 4-at-a-time: entry (i4, l) = rows 4i4..4i4+3, col l.
    for (int i = tid; i < 8 * 32; i += 256) {
        int i4 = i >> 5, l = i & 31, r0 = i4 * 4;
        float p3 = (r0 + 3 < 31) ? pw1[(r0 + 3) * 32 + l] : 0.0f;
        float f3 = (r0 + 3 < 31) ? fw1[(r0 + 3) * 32 + l] : 0.0f;
        s_pw1[i] = make_float4(pw1[r0 * 32 + l], pw1[(r0 + 1) * 32 + l],
                               pw1[(r0 + 2) * 32 + l], p3);
        s_fw1[i] = make_float4(fw1[r0 * 32 + l], fw1[(r0 + 1) * 32 + l],
                               fw1[(r0 + 2) * 32 + l], f3);
        s_pw2[i] = make_float4(pw2[r0 * 32 + l], pw2[(r0 + 1) * 32 + l],
                               pw2[(r0 + 2) * 32 + l], pw2[(r0 + 3) * 32 + l]);
        s_fw2[i] = make_float4(fw2[r0 * 32 + l], fw2[(r0 + 1) * 32 + l],
                               fw2[(r0 + 2) * 32 + l], fw2[(r0 + 3) * 32 + l]);
    }
    if (tid < 32) { s_pb1[tid] = pb1[tid]; s_pb2[tid] = pb2[tid];
                    s_fb1[tid] = fb1[tid]; s_fb2[tid] = fb2[tid]; }
    __syncthreads();

    int lane = tid & 31;
    int w    = tid >> 5;
    int pos0 = (blockIdx.x * 8 + w) * 4;

    float mk[4];
    #pragma unroll
    for (int q = 0; q < 4; q++) {
        int pos = pos0 + q;
        float t = times[pos], v = values[pos];
        mk[q] = mask[pos];
        int m = meas[pos];
        ((float*)&s_x4[w][q])[lane] = combined_lane(t, v, m, lane) * mk[q];
    }
    __syncwarp();

    float acc[4];

    // ---- psi layer 1 ----
    #pragma unroll
    for (int q = 0; q < 4; q++) acc[q] = s_pb1[lane];
    #pragma unroll
    for (int i4 = 0; i4 < 8; i4++) {
        float4 wv = s_pw1[i4 * 32 + lane];
        #pragma unroll
        for (int q = 0; q < 4; q++) {
            float4 xv = s_x4[w][q][i4];
            acc[q] += xv.x * wv.x; acc[q] += xv.y * wv.y;
            acc[q] += xv.z * wv.z; acc[q] += xv.w * wv.w;
        }
    }
    #pragma unroll
    for (int q = 0; q < 4; q++)
        ((float*)&s_h4[w][q])[lane] = fmaxf(acc[q], 0.0f) * mk[q];
    __syncwarp();

    // ---- psi layer 2 ----
    #pragma unroll
    for (int q = 0; q < 4; q++) acc[q] = s_pb2[lane];
    #pragma unroll
    for (int i4 = 0; i4 < 8; i4++) {
        float4 wv = s_pw2[i4 * 32 + lane];
        #pragma unroll
        for (int q = 0; q < 4; q++) {
            float4 xv = s_h4[w][q][i4];
            acc[q] += xv.x * wv.x; acc[q] += xv.y * wv.y;
            acc[q] += xv.z * wv.z; acc[q] += xv.w * wv.w;
        }
    }
    #pragma unroll
    for (int q = 0; q < 4; q++)
        g_enc_psi[(pos0 + q) * 32 + lane] = fmaxf(acc[q], 0.0f) * mk[q];
    __syncwarp();

    // ---- phi layer 1 (re-reads s_x4, overwrites s_h4) ----
    #pragma unroll
    for (int q = 0; q < 4; q++) acc[q] = s_fb1[lane];
    #pragma unroll
    for (int i4 = 0; i4 < 8; i4++) {
        float4 wv = s_fw1[i4 * 32 + lane];
        #pragma unroll
        for (int q = 0; q < 4; q++) {
            float4 xv = s_x4[w][q][i4];
            acc[q] += xv.x * wv.x; acc[q] += xv.y * wv.y;
            acc[q] += xv.z * wv.z; acc[q] += xv.w * wv.w;
        }
    }
    #pragma unroll
    for (int q = 0; q < 4; q++)
        ((float*)&s_h4[w][q])[lane] = fmaxf(acc[q], 0.0f) * mk[q];
    __syncwarp();

    // ---- phi layer 2 ----
    #pragma unroll
    for (int q = 0; q < 4; q++) acc[q] = s_fb2[lane];
    #pragma unroll
    for (int i4 = 0; i4 < 8; i4++) {
        float4 wv = s_fw2[i4 * 32 + lane];
        #pragma unroll
        for (int q = 0; q < 4; q++) {
            float4 xv = s_h4[w][q][i4];
            acc[q] += xv.x * wv.x; acc[q] += xv.y * wv.y;
            acc[q] += xv.z * wv.z; acc[q] += xv.w * wv.w;
        }
    }
    #pragma unroll
    for (int q = 0; q < 4; q++)
        g_enc[(pos0 + q) * 32 + lane] = fmaxf(acc[q], 0.0f) * mk[q];
}

// ---------------------------------------------------------------------------
// K2 v4: cumulative mean, quarters. Grid 16 = (b, qtr) x 512 threads.
// Warp w owns 32 positions (register-resident), streams its share of the
// preceding qtr*512 positions for the cross-block offset. Write-pass chain is
// register-only.
// ---------------------------------------------------------------------------
__global__ __launch_bounds__(512) void k2_cummean(const float* __restrict__ mask)
{
    __shared__ float s_pre[16][32], s_tot[16][32];
    __shared__ float s_rcp[2048];

    int tid  = threadIdx.x;
    int lane = tid & 31;
    int w    = tid >> 5;                   // 0..15
    int b    = blockIdx.x >> 2;
    int qtr  = blockIdx.x & 3;

    for (int i = tid; i < 2048; i += 512) s_rcp[i] = 1.0f / (float)(i + 1);

    const float* src  = g_enc_psi + b * P_ * 32 + lane;
    float*       dst  = g_aggraw  + b * P_ * 32 + lane;
    const float* mptr = mask + b * P_;

    // Stream preceding positions [0, qtr*512): warp w takes slice of qtr*32.
    {
        int slen = qtr * 32;
        int sb   = w * slen;
        float t0 = 0.f, t1 = 0.f, t2 = 0.f, t3 = 0.f;
        for (int j = 0; j < slen; j += 4) {
            t0 += src[(sb + j) * 32];     t1 += src[(sb + j + 1) * 32];
            t2 += src[(sb + j + 2) * 32]; t3 += src[(sb + j + 3) * 32];
        }
        s_pre[w][lane] = (t0 + t1) + (t2 + t3);
    }

    // Own chunk (32 positions, registers)
    int p0 = qtr * 512 + w * 32;
    float vals[32];
    #pragma unroll
    for (int j = 0; j < 32; j++) vals[j] = src[(p0 + j) * 32];

    {
        float t0 = 0.f, t1 = 0.f, t2 = 0.f, t3 = 0.f;
        #pragma unroll
        for (int j = 0; j < 32; j += 4) {
            t0 += vals[j]; t1 += vals[j + 1]; t2 += vals[j + 2]; t3 += vals[j + 3];
        }
        s_tot[w][lane] = (t0 + t1) + (t2 + t3);
    }
    __syncthreads();

    float off = 0.0f;
    #pragma unroll
    for (int k = 0; k < 16; k++) off += s_pre[k][lane];
    for (int k = 0; k < w; k++)  off += s_tot[k][lane];

    float acc = off;
    #pragma unroll
    for (int j = 0; j < 32; j++) {
        int p = p0 + j;
        acc += vals[j];
        dst[p * 32] = acc * s_rcp[p] * mptr[p];
    }
}

// ---------------------------------------------------------------------------
// K3 v3: agg = (agg_raw @ arho + b)*mask; keys = [combined, agg] @ W_k * mask;
// u = exp(preattn). LDS.128 broadcast style like K1. Grid 256 x 256.
// ---------------------------------------------------------------------------
__global__ __launch_bounds__(256) void k3_preattn(
    const float* __restrict__ times, const float* __restrict__ values,
    const int* __restrict__ meas, const float* __restrict__ mask,
    const float* __restrict__ arw, const float* __restrict__ arb,
    const float* __restrict__ wk, const float* __restrict__ wq)
{
    __shared__ float4 s_ar4[8 * 32];       // arho rows packed x4
    __shared__ float4 s_wk4[32 * 32];      // (row 2i2, 2i2+1) x (out l, l+32)
    __shared__ float  s_ab[32], s_wq[64];
    __shared__ float4 s_g4[8][4][8];       // staged aggraw
    __shared__ float2 s_y2[8][4][32];      // staged concat [x(31), agg(32), 0]

    int tid = threadIdx.x;
    for (int i = tid; i < 8 * 32; i += 256) {
        int i4 = i >> 5, l = i & 31, r0 = i4 * 4;
        s_ar4[i] = make_float4(arw[r0 * 32 + l], arw[(r0 + 1) * 32 + l],
                               arw[(r0 + 2) * 32 + l], arw[(r0 + 3) * 32 + l]);
    }
    for (int i = tid; i < 32 * 32; i += 256) {
        int i2 = i >> 5, l = i & 31, r0 = i2 * 2;
        float w2a = (r0 + 1 < 63) ? wk[(r0 + 1) * 64 + l]      : 0.0f;
        float w2b = (r0 + 1 < 63) ? wk[(r0 + 1) * 64 + l + 32] : 0.0f;
        s_wk4[i] = make_float4(wk[r0 * 64 + l], wk[r0 * 64 + l + 32], w2a, w2b);
    }
    if (tid < 32) s_ab[tid] = arb[tid];
    if (tid < 64) s_wq[tid] = wq[tid];
    __syncthreads();

    int lane = tid & 31;
    int w    = tid >> 5;
    int pos0 = (blockIdx.x * 8 + w) * 4;

    float mk[4];
    #pragma unroll
    for (int q = 0; q < 4; q++) {
        int pos = pos0 + q;
        float t = times[pos], v = values[pos];
        mk[q] = mask[pos];
        int m = meas[pos];
        // y[0..31] = combined (lane 31 -> 0)
        ((float*)s_y2[w][q])[lane] = combined_lane(t, v, m, lane);
        ((float*)&s_g4[w][q])[lane] = g_aggraw[pos * 32 + lane];
    }
    __syncwarp();

    // agg matvec (32x32)
    float agg[4];
    #pragma unroll
    for (int q = 0; q < 4; q++) agg[q] = s_ab[lane];
    #pragma unroll
    for (int i4 = 0; i4 < 8; i4++) {
        float4 wv = s_ar4[i4 * 32 + lane];
        #pragma unroll
        for (int q = 0; q < 4; q++) {
            float4 xv = s_g4[w][q][i4];
            agg[q] += xv.x * wv.x; agg[q] += xv.y * wv.y;
            agg[q] += xv.z * wv.z; agg[q] += xv.w * wv.w;
        }
    }
    // y[31 + lane] = agg*mask (covers 31..62); y[63] = 0
    #pragma unroll
    for (int q = 0; q < 4; q++) {
        ((float*)s_y2[w][q])[31 + lane] = agg[q] * mk[q];
        if (lane == 0) ((float*)s_y2[w][q])[63] = 0.0f;
    }
    __syncwarp();

    // keys matvec (63x64): lane computes outputs lane and lane+32
    float a0[4] = {0.f, 0.f, 0.f, 0.f}, a1[4] = {0.f, 0.f, 0.f, 0.f};
    #pragma unroll
    for (int i2 = 0; i2 < 32; i2++) {
        float4 wv = s_wk4[i2 * 32 + lane];
        #pragma unroll
        for (int q = 0; q < 4; q++) {
            float2 yv = s_y2[w][q][i2];
            a0[q] += yv.x * wv.x; a1[q] += yv.x * wv.y;
            a0[q] += yv.y * wv.z; a1[q] += yv.y * wv.w;
        }
    }

    int hh = lane & 3, dd = lane >> 2;
    float q0 = s_wq[hh * 16 + dd], q1 = s_wq[hh * 16 + dd + 8];
    #pragma unroll
    for (int q = 0; q < 4; q++) {
        float part = a0[q] * mk[q] * q0 + a1[q] * mk[q] * q1;
        part += __shfl_xor_sync(FULL, part, 4);
        part += __shfl_xor_sync(FULL, part, 8);
        part += __shfl_xor_sync(FULL, part, 16);
        float pre = part * 0.25f * mk[q];
        if (lane < 4) g_u[(pos0 + q) * 4 + lane] = expf(pre);
    }
}

// ---------------------------------------------------------------------------
// K4 v4: causal prefix sums, quarters. Grid 64 = (b,h,qtr) x 512 threads.
// Warp w owns 32 positions; BOTH u and u*enc register-resident so the
// write-pass chains are register-only (no LDG in the dependency chain).
// ---------------------------------------------------------------------------
__global__ __launch_bounds__(512) void k4_scan()
{
    __shared__ float s_pre[16][32], s_tot[16][32];
    __shared__ float s_preu[16], s_totu[16];

    int tid  = threadIdx.x;
    int lane = tid & 31;
    int w    = tid >> 5;                 // 0..15
    int bh   = blockIdx.x >> 2;
    int qtr  = blockIdx.x & 3;
    int b    = bh >> 2, h = bh & 3;

    const float* up = g_u   + b * P_ * 4 + h;     // up[p*4]
    const float* ep = g_enc + b * P_ * 32 + lane; // ep[p*32]

    // Stream preceding positions [0, qtr*512): warp w takes slice of qtr*32.
    {
        int slen = qtr * 32;
        int sb   = w * slen;
        float t0 = 0.f, t1 = 0.f, t2 = 0.f, t3 = 0.f;
        float u0 = 0.f, u1 = 0.f, u2 = 0.f, u3 = 0.f;
        for (int j = 0; j < slen; j += 4) {
            float ua = up[(sb + j) * 4],     ub = up[(sb + j + 1) * 4];
            float uc = up[(sb + j + 2) * 4], ud = up[(sb + j + 3) * 4];
            t0 += ua * ep[(sb + j) * 32];     t1 += ub * ep[(sb + j + 1) * 32];
            t2 += uc * ep[(sb + j + 2) * 32]; t3 += ud * ep[(sb + j + 3) * 32];
            u0 += ua; u1 += ub; u2 += uc; u3 += ud;
        }
        s_pre[w][lane] = (t0 + t1) + (t2 + t3);
        if (lane == 0) s_preu[w] = (u0 + u1) + (u2 + u3);
    }

    // Own chunk (32 positions): u and u*enc both register-resident.
    int p0 = qtr * 512 + w * 32;
    float uv[32], vals[32];
    #pragma unroll
    for (int j = 0; j < 32; j++) uv[j] = up[(p0 + j) * 4];
    #pragma unroll
    for (int j = 0; j < 32; j++) vals[j] = uv[j] * ep[(p0 + j) * 32];

    {
        float t0 = 0.f, t1 = 0.f, t2 = 0.f, t3 = 0.f;
        float u0 = 0.f, u1 = 0.f, u2 = 0.f, u3 = 0.f;
        #pragma unroll
        for (int j = 0; j < 32; j += 4) {
            t0 += vals[j]; t1 += vals[j + 1]; t2 += vals[j + 2]; t3 += vals[j + 3];
            u0 += uv[j];   u1 += uv[j + 1];   u2 += uv[j + 2];   u3 += uv[j + 3];
        }
        s_tot[w][lane] = (t0 + t1) + (t2 + t3);
        if (lane == 0) s_totu[w] = (u0 + u1) + (u2 + u3);
    }
    __syncthreads();

    float offn = 0.0f, offu = 0.0f;
    #pragma unroll
    for (int k = 0; k < 16; k++) { offn += s_pre[k][lane]; offu += s_preu[k]; }
    for (int k = 0; k < w; k++)  { offn += s_tot[k][lane]; offu += s_totu[k]; }

    float* nq = g_num + (b * P_ * 4 + h) * 32 + lane;  // nq[p*128]
    float* dq = g_den + b * P_ * 4 + h;                // dq[p*4]

    float accn = offn, accu = offu;
    #pragma unroll
    for (int j = 0; j < 32; j++) {
        int p = p0 + j;
        accn += vals[j];
        accu += uv[j];
        nq[p * 128] = accn;
        if (lane == 0) dq[p * 4] = accu;
    }
}

// ---------------------------------------------------------------------------
// K5 v2: rho MLP with packed f32x2 FFMA (unchanged from R5).
// ---------------------------------------------------------------------------
__global__ __launch_bounds__(256) void k5_rho(
    const float* __restrict__ mask,
    const float* __restrict__ rw1, const float* __restrict__ rb1,
    const float* __restrict__ rw2, const float* __restrict__ rb2,
    float* __restrict__ out)
{
    extern __shared__ char sm5[];
    float4* s_w1 = (float4*)sm5;                    // 2048 float4 = 32KB
    float4* s_w2 = (float4*)(sm5 + 32768);          // 1024 float4 = 16KB
    ull*    s_a  = (ull*)   (sm5 + 49152);          // 8192 ull    = 64KB
    ull*    s_h  = (ull*)   (sm5 + 114688);         // 4096 ull    = 32KB

    int tid = threadIdx.x;
    int w = tid >> 5, lane = tid & 31;

    for (int i = tid; i < 2048; i += 256) {
        int kp = i >> 5, l = i & 31, k = kp * 2;
        s_w1[i] = make_float4(rw1[k * 64 + l],        rw1[k * 64 + l + 32],
                              rw1[(k + 1) * 64 + l],  rw1[(k + 1) * 64 + l + 32]);
    }
    for (int i = tid; i < 1024; i += 256) {
        int kp = i >> 5, l = i & 31, k = kp * 2;
        s_w2[i] = make_float4(rw2[k * 64 + l],        rw2[k * 64 + l + 32],
                              rw2[(k + 1) * 64 + l],  rw2[(k + 1) * 64 + l + 32]);
    }

    int pos0 = (blockIdx.x * 8 + w) * 8;
    float mks[8];
    #pragma unroll
    for (int q = 0; q < 8; q++) {
        int pos = pos0 + q;
        float mk = mask[pos];
        mks[q] = mk;
        float mk2 = mk * mk;
        #pragma unroll
        for (int h4 = 0; h4 < 4; h4++) {
            float sc = __fdividef(mk2, g_den[pos * 4 + h4]);
            float v  = g_num[(pos * 4 + h4) * 32 + lane] * sc;
            s_a[(w * 8 + q) * 128 + h4 * 32 + lane] = pack2(v, v);
        }
    }
    __syncthreads();

    ull acc[8];
    {
        ull bini = pack2(rb1[lane], rb1[lane + 32]);
        #pragma unroll
        for (int q = 0; q < 8; q++) acc[q] = bini;
    }

    const ulonglong2* w1v = (const ulonglong2*)s_w1;
    const ulonglong2* av  = (const ulonglong2*)s_a;
    #pragma unroll 4
    for (int kp = 0; kp < 64; kp++) {
        ulonglong2 wv = w1v[kp * 32 + lane];
        #pragma unroll
        for (int q = 0; q < 8; q++) {
            ulonglong2 a2 = av[(w * 8 + q) * 64 + kp];
            acc[q] = ffma2(a2.x, wv.x, acc[q]);
            acc[q] = ffma2(a2.y, wv.y, acc[q]);
        }
    }

    #pragma unroll
    for (int q = 0; q < 8; q++) {
        float r0, r1; unpack2(acc[q], r0, r1);
        r0 = fmaxf(r0, 0.0f) * mks[q];
        r1 = fmaxf(r1, 0.0f) * mks[q];
        s_h[(w * 8 + q) * 64 + lane]      = pack2(r0, r0);
        s_h[(w * 8 + q) * 64 + lane + 32] = pack2(r1, r1);
    }
    __syncwarp();

    {
        ull bini = pack2(rb2[lane], rb2[lane + 32]);
        #pragma unroll
        for (int q = 0; q < 8; q++) acc[q] = bini;
    }

    const ulonglong2* w2v = (const ulonglong2*)s_w2;
    const ulonglong2* hv  = (const ulonglong2*)s_h;
    #pragma unroll 4
    for (int kp = 0; kp < 32; kp++) {
        ulonglong2 wv = w2v[kp * 32 + lane];
        #pragma unroll
        for (int q = 0; q < 8; q++) {
            ulonglong2 a2 = hv[(w * 8 + q) * 32 + kp];
            acc[q] = ffma2(a2.x, wv.x, acc[q]);
            acc[q] = ffma2(a2.y, wv.y, acc[q]);
        }
    }

    #pragma unroll
    for (int q = 0; q < 8; q++) {
        int pos = pos0 + q;
        float r0, r1; unpack2(acc[q], r0, r1);
        out[pos * 64 + lane]      = fmaxf(r0, 0.0f) * mks[q];
        out[pos * 64 + lane + 32] = fmaxf(r1, 0.0f) * mks[q];
    }
}

// ---------------------------------------------------------------------------
extern "C" void kernel_launch(void* const* d_in, const int* in_sizes, int n_in,
                              void* d_out, int out_size)
{
    const float* times   = (const float*)d_in[0];
    const float* values  = (const float*)d_in[1];
    const int*   meas    = (const int*)  d_in[2];
    const float* mask    = (const float*)d_in[3];
    const float* psi_w1  = (const float*)d_in[4];
    const float* psi_b1  = (const float*)d_in[5];
    const float* psi_w2  = (const float*)d_in[6];
    const float* psi_b2  = (const float*)d_in[7];
    const float* arho_w  = (const float*)d_in[8];
    const float* arho_b  = (const float*)d_in[9];
    const float* W_k     = (const float*)d_in[10];
    const float* W_q     = (const float*)d_in[11];
    const float* phi_w1  = (const float*)d_in[12];
    const float* phi_b1  = (const float*)d_in[13];
    const float* phi_w2  = (const float*)d_in[14];
    const float* phi_b2  = (const float*)d_in[15];
    const float* rho_w1  = (const float*)d_in[16];
    const float* rho_b1  = (const float*)d_in[17];
    const float* rho_w2  = (const float*)d_in[18];
    const float* rho_b2  = (const float*)d_in[19];
    float* out = (float*)d_out;

    cudaFuncSetAttribute(k5_rho, cudaFuncAttributeMaxDynamicSharedMemorySize, 147456);

    k1_feat_mlps<<<256, 256>>>(times, values, meas, mask,
                               psi_w1, psi_b1, psi_w2, psi_b2,
                               phi_w1, phi_b1, phi_w2, phi_b2);
    k2_cummean<<<16, 512>>>(mask);
    k3_preattn<<<256, 256>>>(times, values, meas, mask,
                             arho_w, arho_b, W_k, W_q);
    k4_scan<<<64, 512>>>();
    k5_rho<<<128, 256, 147456>>>(mask, rho_w1, rho_b1, rho_w2, rho_b2, out);
}

// round 9
// speedup vs baseline: 3.6434x; 1.0471x over previous
#include <cuda_runtime.h>
#include <math.h>

#define FULL 0xffffffffu
typedef unsigned long long ull;

// Problem constants
constexpr int B_ = 4;
constexpr int P_ = 2048;
constexpr int NPOS = B_ * P_;           // 8192
constexpr int NCHUNK = 64;              // 32-position chunks per sequence

// Scratch (device globals; no allocation in kernel_launch)
__device__ float g_enc_psi[NPOS * 32];
__device__ float g_enc[NPOS * 32];
__device__ float g_u[NPOS * 4];
__device__ float g_num[NPOS * 4 * 32];
__device__ float g_den[NPOS * 4];
__device__ float g_ct2[B_ * NCHUNK * 32];       // chunk totals of enc_psi
__device__ float g_ct4n[16 * NCHUNK * 32];      // chunk totals of u*enc per (b,h)
__device__ float g_ct4d[16 * NCHUNK];           // chunk totals of u per (b,h)

// ---- f32x2 packed helpers (sm_103a FFMA2 path) ------------------------------
__device__ __forceinline__ ull pack2(float x, float y) {
    ull r; asm("mov.b64 %0, {%1, %2};" : "=l"(r) : "f"(x), "f"(y)); return r;
}
__device__ __forceinline__ void unpack2(ull v, float& x, float& y) {
    asm("mov.b64 {%0, %1}, %2;" : "=f"(x), "=f"(y) : "l"(v));
}
__device__ __forceinline__ ull ffma2(ull a, ull b, ull c) {
    ull d; asm("fma.rn.f32x2 %0, %1, %2, %3;" : "=l"(d) : "l"(a), "l"(b), "l"(c));
    return d;
}

// combined[lane] for one position
__device__ __forceinline__ float combined_lane(float t, float v, int m, int lane) {
    if (lane < 8) {
        float sc;
        switch (lane >> 1) {
            case 0:  sc = 1.0f;   break;
            case 1:  sc = 0.1f;   break;
            case 2:  sc = 0.01f;  break;
            default: sc = 0.001f; break;
        }
        float r = t * sc;
        return (lane & 1) ? cosf(r) : sinf(r);
    } else if (lane == 8) {
        return v;
    } else if (lane < 31) {
        return (m == lane - 8) ? 1.0f : 0.0f;
    }
    return 0.0f;
}

// ---------------------------------------------------------------------------
// K1: features + psi MLP + phi MLP + enc_psi chunk totals.
// Grid 256 (block = one 32-position chunk) x 256 threads; warp = 4 positions.
// ---------------------------------------------------------------------------
__global__ __launch_bounds__(256) void k1_feat_mlps(
    const float* __restrict__ times, const float* __restrict__ values,
    const int* __restrict__ meas, const float* __restrict__ mask,
    const float* __restrict__ pw1, const float* __restrict__ pb1,
    const float* __restrict__ pw2, const float* __restrict__ pb2,
    const float* __restrict__ fw1, const float* __restrict__ fb1,
    const float* __restrict__ fw2, const float* __restrict__ fb2)
{
    __shared__ float4 s_pw1[8 * 32], s_pw2[8 * 32];
    __shared__ float4 s_fw1[8 * 32], s_fw2[8 * 32];
    __shared__ float  s_pb1[32], s_pb2[32], s_fb1[32], s_fb2[32];
    __shared__ float4 s_x4[8][4][8];
    __shared__ float4 s_h4[8][4][8];
    __shared__ float  s_part[8][32];     // per-warp enc_psi partial sums

    int tid = threadIdx.x;
    for (int i = tid; i < 8 * 32; i += 256) {
        int i4 = i >> 5, l = i & 31, r0 = i4 * 4;
        float p3 = (r0 + 3 < 31) ? pw1[(r0 + 3) * 32 + l] : 0.0f;
        float f3 = (r0 + 3 < 31) ? fw1[(r0 + 3) * 32 + l] : 0.0f;
        s_pw1[i] = make_float4(pw1[r0 * 32 + l], pw1[(r0 + 1) * 32 + l],
                               pw1[(r0 + 2) * 32 + l], p3);
        s_fw1[i] = make_float4(fw1[r0 * 32 + l], fw1[(r0 + 1) * 32 + l],
                               fw1[(r0 + 2) * 32 + l], f3);
        s_pw2[i] = make_float4(pw2[r0 * 32 + l], pw2[(r0 + 1) * 32 + l],
                               pw2[(r0 + 2) * 32 + l], pw2[(r0 + 3) * 32 + l]);
        s_fw2[i] = make_float4(fw2[r0 * 32 + l], fw2[(r0 + 1) * 32 + l],
                               fw2[(r0 + 2) * 32 + l], fw2[(r0 + 3) * 32 + l]);
    }
    if (tid < 32) { s_pb1[tid] = pb1[tid]; s_pb2[tid] = pb2[tid];
                    s_fb1[tid] = fb1[tid]; s_fb2[tid] = fb2[tid]; }
    __syncthreads();

    int lane = tid & 31;
    int w    = tid >> 5;
    int pos0 = blockIdx.x * 32 + w * 4;
    int b    = blockIdx.x >> 6;
    int chunk = blockIdx.x & 63;

    float mk[4];
    #pragma unroll
    for (int q = 0; q < 4; q++) {
        int pos = pos0 + q;
        float t = times[pos], v = values[pos];
        mk[q] = mask[pos];
        int m = meas[pos];
        ((float*)&s_x4[w][q])[lane] = combined_lane(t, v, m, lane) * mk[q];
    }
    __syncwarp();

    float acc[4];

    // psi layer 1
    #pragma unroll
    for (int q = 0; q < 4; q++) acc[q] = s_pb1[lane];
    #pragma unroll
    for (int i4 = 0; i4 < 8; i4++) {
        float4 wv = s_pw1[i4 * 32 + lane];
        #pragma unroll
        for (int q = 0; q < 4; q++) {
            float4 xv = s_x4[w][q][i4];
            acc[q] += xv.x * wv.x; acc[q] += xv.y * wv.y;
            acc[q] += xv.z * wv.z; acc[q] += xv.w * wv.w;
        }
    }
    #pragma unroll
    for (int q = 0; q < 4; q++)
        ((float*)&s_h4[w][q])[lane] = fmaxf(acc[q], 0.0f) * mk[q];
    __syncwarp();

    // psi layer 2 (+ chunk partial)
    #pragma unroll
    for (int q = 0; q < 4; q++) acc[q] = s_pb2[lane];
    #pragma unroll
    for (int i4 = 0; i4 < 8; i4++) {
        float4 wv = s_pw2[i4 * 32 + lane];
        #pragma unroll
        for (int q = 0; q < 4; q++) {
            float4 xv = s_h4[w][q][i4];
            acc[q] += xv.x * wv.x; acc[q] += xv.y * wv.y;
            acc[q] += xv.z * wv.z; acc[q] += xv.w * wv.w;
        }
    }
    float psum = 0.0f;
    #pragma unroll
    for (int q = 0; q < 4; q++) {
        float ev = fmaxf(acc[q], 0.0f) * mk[q];
        g_enc_psi[(pos0 + q) * 32 + lane] = ev;
        psum += ev;
    }
    s_part[w][lane] = psum;
    __syncwarp();

    // phi layer 1
    #pragma unroll
    for (int q = 0; q < 4; q++) acc[q] = s_fb1[lane];
    #pragma unroll
    for (int i4 = 0; i4 < 8; i4++) {
        float4 wv = s_fw1[i4 * 32 + lane];
        #pragma unroll
        for (int q = 0; q < 4; q++) {
            float4 xv = s_x4[w][q][i4];
            acc[q] += xv.x * wv.x; acc[q] += xv.y * wv.y;
            acc[q] += xv.z * wv.z; acc[q] += xv.w * wv.w;
        }
    }
    #pragma unroll
    for (int q = 0; q < 4; q++)
        ((float*)&s_h4[w][q])[lane] = fmaxf(acc[q], 0.0f) * mk[q];
    __syncwarp();

    // phi layer 2
    #pragma unroll
    for (int q = 0; q < 4; q++) acc[q] = s_fb2[lane];
    #pragma unroll
    for (int i4 = 0; i4 < 8; i4++) {
        float4 wv = s_fw2[i4 * 32 + lane];
        #pragma unroll
        for (int q = 0; q < 4; q++) {
            float4 xv = s_h4[w][q][i4];
            acc[q] += xv.x * wv.x; acc[q] += xv.y * wv.y;
            acc[q] += xv.z * wv.z; acc[q] += xv.w * wv.w;
        }
    }
    #pragma unroll
    for (int q = 0; q < 4; q++)
        g_enc[(pos0 + q) * 32 + lane] = fmaxf(acc[q], 0.0f) * mk[q];

    // chunk total of enc_psi
    __syncthreads();
    if (w == 0) {
        float t = 0.0f;
        #pragma unroll
        for (int w2 = 0; w2 < 8; w2++) t += s_part[w2][lane];
        g_ct2[(b * NCHUNK + chunk) * 32 + lane] = t;
    }
}

// ---------------------------------------------------------------------------
// K3: inline aggraw (cumsum via g_ct2 chunk offsets + within-chunk prefix),
// agg matvec, keys matvec, preattn, u, and k4 chunk totals (u*enc, u).
// Grid 256 (block = chunk) x 256 threads.
// ---------------------------------------------------------------------------
__global__ __launch_bounds__(256) void k3_preattn(
    const float* __restrict__ times, const float* __restrict__ values,
    const int* __restrict__ meas, const float* __restrict__ mask,
    const float* __restrict__ arw, const float* __restrict__ arb,
    const float* __restrict__ wk, const float* __restrict__ wq)
{
    __shared__ float4 s_ar4[8 * 32];
    __shared__ float4 s_wk4[32 * 32];
    __shared__ float  s_ab[32], s_wq[64];
    __shared__ float4 s_g4[8][4][8];
    __shared__ float2 s_y2[8][4][32];
    __shared__ float  s_wp[8][32];
    __shared__ float  s_pn[8][4][32];
    __shared__ float  s_pd[8][4];

    int tid = threadIdx.x;
    for (int i = tid; i < 8 * 32; i += 256) {
        int i4 = i >> 5, l = i & 31, r0 = i4 * 4;
        s_ar4[i] = make_float4(arw[r0 * 32 + l], arw[(r0 + 1) * 32 + l],
                               arw[(r0 + 2) * 32 + l], arw[(r0 + 3) * 32 + l]);
    }
    for (int i = tid; i < 32 * 32; i += 256) {
        int i2 = i >> 5, l = i & 31, r0 = i2 * 2;
        float w2a = (r0 + 1 < 63) ? wk[(r0 + 1) * 64 + l]      : 0.0f;
        float w2b = (r0 + 1 < 63) ? wk[(r0 + 1) * 64 + l + 32] : 0.0f;
        s_wk4[i] = make_float4(wk[r0 * 64 + l], wk[r0 * 64 + l + 32], w2a, w2b);
    }
    if (tid < 32) s_ab[tid] = arb[tid];
    if (tid < 64) s_wq[tid] = wq[tid];

    int lane  = tid & 31;
    int w     = tid >> 5;
    int b     = blockIdx.x >> 6;
    int chunk = blockIdx.x & 63;
    int pos0  = blockIdx.x * 32 + w * 4;        // global position
    int lp0   = chunk * 32 + w * 4;             // LOCAL (within-sequence) position

    // Stage raw combined; load own-chunk enc_psi; within-warp prefix.
    float mk[4], cq[4];
    {
        float eq[4];
        #pragma unroll
        for (int q = 0; q < 4; q++) {
            int pos = pos0 + q;
            float t = times[pos], v = values[pos];
            mk[q] = mask[pos];
            int m = meas[pos];
            ((float*)s_y2[w][q])[lane] = combined_lane(t, v, m, lane);
            eq[q] = g_enc_psi[pos * 32 + lane];
        }
        cq[0] = eq[0];
        cq[1] = cq[0] + eq[1];
        cq[2] = cq[1] + eq[2];
        cq[3] = cq[2] + eq[3];
        s_wp[w][lane] = cq[3];
    }
    __syncthreads();   // covers weights, s_y2 low, s_wp

    // exclusive offset: preceding chunks (g_ct2) + preceding warps
    float off;
    {
        const float* ct = g_ct2 + (b * NCHUNK) * 32 + lane;
        float o0 = 0.f, o1 = 0.f, o2 = 0.f, o3 = 0.f;
        int k = 0;
        for (; k + 4 <= chunk; k += 4) {
            o0 += ct[k * 32];       o1 += ct[(k + 1) * 32];
            o2 += ct[(k + 2) * 32]; o3 += ct[(k + 3) * 32];
        }
        for (; k < chunk; k++) o0 += ct[k * 32];
        off = (o0 + o1) + (o2 + o3);
    }
    #pragma unroll
    for (int w2 = 0; w2 < 8; w2++)
        if (w2 < w) off += s_wp[w2][lane];

    // aggraw = cumsum / (LOCAL count) * mask -> staged for broadcast matvec
    #pragma unroll
    for (int q = 0; q < 4; q++) {
        float cum = off + cq[q];
        float agr = __fdividef(cum, (float)(lp0 + q + 1)) * mk[q];
        ((float*)&s_g4[w][q])[lane] = agr;
    }
    __syncwarp();

    // agg matvec (32x32)
    float agg[4];
    #pragma unroll
    for (int q = 0; q < 4; q++) agg[q] = s_ab[lane];
    #pragma unroll
    for (int i4 = 0; i4 < 8; i4++) {
        float4 wv = s_ar4[i4 * 32 + lane];
        #pragma unroll
        for (int q = 0; q < 4; q++) {
            float4 xv = s_g4[w][q][i4];
            agg[q] += xv.x * wv.x; agg[q] += xv.y * wv.y;
            agg[q] += xv.z * wv.z; agg[q] += xv.w * wv.w;
        }
    }
    #pragma unroll
    for (int q = 0; q < 4; q++) {
        ((float*)s_y2[w][q])[31 + lane] = agg[q] * mk[q];
        if (lane == 0) ((float*)s_y2[w][q])[63] = 0.0f;
    }
    __syncwarp();

    // keys matvec (63x64)
    float a0[4] = {0.f, 0.f, 0.f, 0.f}, a1[4] = {0.f, 0.f, 0.f, 0.f};
    #pragma unroll
    for (int i2 = 0; i2 < 32; i2++) {
        float4 wv = s_wk4[i2 * 32 + lane];
        #pragma unroll
        for (int q = 0; q < 4; q++) {
            float2 yv = s_y2[w][q][i2];
            a0[q] += yv.x * wv.x; a1[q] += yv.x * wv.y;
            a0[q] += yv.y * wv.z; a1[q] += yv.y * wv.w;
        }
    }

    int hh = lane & 3, dd = lane >> 2;
    float q0 = s_wq[hh * 16 + dd], q1 = s_wq[hh * 16 + dd + 8];
    float ufull[4];
    #pragma unroll
    for (int q = 0; q < 4; q++) {
        float part = a0[q] * mk[q] * q0 + a1[q] * mk[q] * q1;
        part += __shfl_xor_sync(FULL, part, 4);
        part += __shfl_xor_sync(FULL, part, 8);
        part += __shfl_xor_sync(FULL, part, 16);
        float pre = part * 0.25f * mk[q];
        ufull[q] = expf(pre);                    // lane l holds head l&3
        if (lane < 4) g_u[(pos0 + q) * 4 + lane] = ufull[q];
    }

    // k4 chunk totals: pn[h][lane] = sum_q u[q][h]*enc[q][lane]; pd[h] = sum_q u[q][h]
    {
        float e2q[4];
        #pragma unroll
        for (int q = 0; q < 4; q++) e2q[q] = g_enc[(pos0 + q) * 32 + lane];
        #pragma unroll
        for (int h = 0; h < 4; h++) {
            float s = 0.0f;
            #pragma unroll
            for (int q = 0; q < 4; q++)
                s += __shfl_sync(FULL, ufull[q], h) * e2q[q];
            s_pn[w][h][lane] = s;
        }
        if (lane < 4)
            s_pd[w][lane] = ufull[0] + ufull[1] + ufull[2] + ufull[3];
    }
    __syncthreads();

    if (w < 4) {
        int h = w;
        float t = 0.0f;
        #pragma unroll
        for (int w2 = 0; w2 < 8; w2++) t += s_pn[w2][h][lane];
        g_ct4n[((b * 4 + h) * NCHUNK + chunk) * 32 + lane] = t;
        if (lane == 0) {
            float td = 0.0f;
            #pragma unroll
            for (int w2 = 0; w2 < 8; w2++) td += s_pd[w2][h];
            g_ct4d[(b * 4 + h) * NCHUNK + chunk] = td;
        }
    }
}

// ---------------------------------------------------------------------------
// K4b: pure offset + write. One warp per (b,h,chunk) = 1024 warps = 128
// blocks x 256 threads. Offset from precomputed chunk totals (balanced,
// coalesced); write pass is a register-only 32-step chain.
// ---------------------------------------------------------------------------
__global__ __launch_bounds__(256) void k4_scan()
{
    int tid  = threadIdx.x;
    int lane = tid & 31;
    int w    = tid >> 5;
    int wg   = blockIdx.x * 8 + w;       // 0..1023
    int bh   = wg >> 6;
    int c    = wg & 63;
    int b    = bh >> 2, h = bh & 3;

    // num offset: sum of preceding chunk totals (coalesced)
    float offn;
    {
        const float* ct = g_ct4n + (bh * NCHUNK) * 32 + lane;
        float o0 = 0.f, o1 = 0.f, o2 = 0.f, o3 = 0.f;
        int k = 0;
        for (; k + 4 <= c; k += 4) {
            o0 += ct[k * 32];       o1 += ct[(k + 1) * 32];
            o2 += ct[(k + 2) * 32]; o3 += ct[(k + 3) * 32];
        }
        for (; k < c; k++) o0 += ct[k * 32];
        offn = (o0 + o1) + (o2 + o3);
    }
    // den offset: lanes cover chunk indices, xor-reduce
    float offd;
    {
        const float* cd = g_ct4d + bh * NCHUNK;
        float myd = 0.0f;
        if (lane < c)      myd  = cd[lane];
        if (lane + 32 < c) myd += cd[lane + 32];
        #pragma unroll
        for (int o = 16; o >= 1; o >>= 1) myd += __shfl_xor_sync(FULL, myd, o);
        offd = myd;
    }

    const float* up = g_u   + b * P_ * 4 + h;
    const float* ep = g_enc + b * P_ * 32 + lane;
    int p0 = c * 32;

    float uv[32], vals[32];
    #pragma unroll
    for (int j = 0; j < 32; j++) uv[j] = up[(p0 + j) * 4];
    #pragma unroll
    for (int j = 0; j < 32; j++) vals[j] = uv[j] * ep[(p0 + j) * 32];

    float* nq = g_num + (b * P_ * 4 + h) * 32 + lane;
    float* dq = g_den + b * P_ * 4 + h;

    float accn = offn, accu = offd;
    #pragma unroll
    for (int j = 0; j < 32; j++) {
        int p = p0 + j;
        accn += vals[j];
        accu += uv[j];
        nq[p * 128] = accn;
        if (lane == 0) dq[p * 4] = accu;
    }
}

// ---------------------------------------------------------------------------
// K5: rho MLP with packed f32x2 FFMA (unchanged).
// ---------------------------------------------------------------------------
__global__ __launch_bounds__(256) void k5_rho(
    const float* __restrict__ mask,
    const float* __restrict__ rw1, const float* __restrict__ rb1,
    const float* __restrict__ rw2, const float* __restrict__ rb2,
    float* __restrict__ out)
{
    extern __shared__ char sm5[];
    float4* s_w1 = (float4*)sm5;                    // 32KB
    float4* s_w2 = (float4*)(sm5 + 32768);          // 16KB
    ull*    s_a  = (ull*)   (sm5 + 49152);          // 64KB
    ull*    s_h  = (ull*)   (sm5 + 114688);         // 32KB

    int tid = threadIdx.x;
    int w = tid >> 5, lane = tid & 31;

    for (int i = tid; i < 2048; i += 256) {
        int kp = i >> 5, l = i & 31, k = kp * 2;
        s_w1[i] = make_float4(rw1[k * 64 + l],        rw1[k * 64 + l + 32],
                              rw1[(k + 1) * 64 + l],  rw1[(k + 1) * 64 + l + 32]);
    }
    for (int i = tid; i < 1024; i += 256) {
        int kp = i >> 5, l = i & 31, k = kp * 2;
        s_w2[i] = make_float4(rw2[k * 64 + l],        rw2[k * 64 + l + 32],
                              rw2[(k + 1) * 64 + l],  rw2[(k + 1) * 64 + l + 32]);
    }

    int pos0 = (blockIdx.x * 8 + w) * 8;
    float mks[8];
    #pragma unroll
    for (int q = 0; q < 8; q++) {
        int pos = pos0 + q;
        float mk = mask[pos];
        mks[q] = mk;
        float mk2 = mk * mk;
        #pragma unroll
        for (int h4 = 0; h4 < 4; h4++) {
            float sc = __fdividef(mk2, g_den[pos * 4 + h4]);
            float v  = g_num[(pos * 4 + h4) * 32 + lane] * sc;
            s_a[(w * 8 + q) * 128 + h4 * 32 + lane] = pack2(v, v);
        }
    }
    __syncthreads();

    ull acc[8];
    {
        ull bini = pack2(rb1[lane], rb1[lane + 32]);
        #pragma unroll
        for (int q = 0; q < 8; q++) acc[q] = bini;
    }

    const ulonglong2* w1v = (const ulonglong2*)s_w1;
    const ulonglong2* av  = (const ulonglong2*)s_a;
    #pragma unroll 4
    for (int kp = 0; kp < 64; kp++) {
        ulonglong2 wv = w1v[kp * 32 + lane];
        #pragma unroll
        for (int q = 0; q < 8; q++) {
            ulonglong2 a2 = av[(w * 8 + q) * 64 + kp];
            acc[q] = ffma2(a2.x, wv.x, acc[q]);
            acc[q] = ffma2(a2.y, wv.y, acc[q]);
        }
    }

    #pragma unroll
    for (int q = 0; q < 8; q++) {
        float r0, r1; unpack2(acc[q], r0, r1);
        r0 = fmaxf(r0, 0.0f) * mks[q];
        r1 = fmaxf(r1, 0.0f) * mks[q];
        s_h[(w * 8 + q) * 64 + lane]      = pack2(r0, r0);
        s_h[(w * 8 + q) * 64 + lane + 32] = pack2(r1, r1);
    }
    __syncwarp();

    {
        ull bini = pack2(rb2[lane], rb2[lane + 32]);
        #pragma unroll
        for (int q = 0; q < 8; q++) acc[q] = bini;
    }

    const ulonglong2* w2v = (const ulonglong2*)s_w2;
    const ulonglong2* hv  = (const ulonglong2*)s_h;
    #pragma unroll 4
    for (int kp = 0; kp < 32; kp++) {
        ulonglong2 wv = w2v[kp * 32 + lane];
        #pragma unroll
        for (int q = 0; q < 8; q++) {
            ulonglong2 a2 = hv[(w * 8 + q) * 32 + kp];
            acc[q] = ffma2(a2.x, wv.x, acc[q]);
            acc[q] = ffma2(a2.y, wv.y, acc[q]);
        }
    }

    #pragma unroll
    for (int q = 0; q < 8; q++) {
        int pos = pos0 + q;
        float r0, r1; unpack2(acc[q], r0, r1);
        out[pos * 64 + lane]      = fmaxf(r0, 0.0f) * mks[q];
        out[pos * 64 + lane + 32] = fmaxf(r1, 0.0f) * mks[q];
    }
}

// ---------------------------------------------------------------------------
extern "C" void kernel_launch(void* const* d_in, const int* in_sizes, int n_in,
                              void* d_out, int out_size)
{
    const float* times   = (const float*)d_in[0];
    const float* values  = (const float*)d_in[1];
    const int*   meas    = (const int*)  d_in[2];
    const float* mask    = (const float*)d_in[3];
    const float* psi_w1  = (const float*)d_in[4];
    const float* psi_b1  = (const float*)d_in[5];
    const float* psi_w2  = (const float*)d_in[6];
    const float* psi_b2  = (const float*)d_in[7];
    const float* arho_w  = (const float*)d_in[8];
    const float* arho_b  = (const float*)d_in[9];
    const float* W_k     = (const float*)d_in[10];
    const float* W_q     = (const float*)d_in[11];
    const float* phi_w1  = (const float*)d_in[12];
    const float* phi_b1  = (const float*)d_in[13];
    const float* phi_w2  = (const float*)d_in[14];
    const float* phi_b2  = (const float*)d_in[15];
    const float* rho_w1  = (const float*)d_in[16];
    const float* rho_b1  = (const float*)d_in[17];
    const float* rho_w2  = (const float*)d_in[18];
    const float* rho_b2  = (const float*)d_in[19];
    float* out = (float*)d_out;

    cudaFuncSetAttribute(k5_rho, cudaFuncAttributeMaxDynamicSharedMemorySize, 147456);

    k1_feat_mlps<<<256, 256>>>(times, values, meas, mask,
                               psi_w1, psi_b1, psi_w2, psi_b2,
                               phi_w1, phi_b1, phi_w2, phi_b2);
    k3_preattn<<<256, 256>>>(times, values, meas, mask,
                             arho_w, arho_b, W_k, W_q);
    k4_scan<<<128, 256>>>();
    k5_rho<<<128, 256, 147456>>>(mask, rho_w1, rho_b1, rho_w2, rho_b2, out);
}